// round 1
// baseline (speedup 1.0000x reference)
#include <cuda_runtime.h>
#include <math.h>

// Problem constants
constexpr int kNQ = 8192;
constexpr int kNT = 8192;
constexpr int kD  = 128;
constexpr int kEC = 262144;
constexpr int kEQ = 262144;
constexpr int kET = 262144;

constexpr size_t SZ = (size_t)kNQ * kD;   // 1,048,576 floats per node matrix

// ---- scratch layout (floats) ----
constexpr size_t O_XQ_AC = 0;
constexpr size_t O_XT_AC = 1*SZ;
constexpr size_t O_XQ_VC = 2*SZ;
constexpr size_t O_XT_VC = 3*SZ;
constexpr size_t O_XT2Q  = 4*SZ;
constexpr size_t O_XQ2T  = 5*SZ;
constexpr size_t O_XQM   = 6*SZ;
constexpr size_t O_XTM   = 7*SZ;
constexpr size_t O_PS_T  = 8*SZ;
constexpr size_t O_PD_T  = 9*SZ;
constexpr size_t O_PS_Q  = 10*SZ;
constexpr size_t O_PD_Q  = 11*SZ;
constexpr size_t O_LC    = 12*SZ;
constexpr size_t O_LT    = O_LC + kEC;
constexpr size_t O_LQ    = O_LT + kET;
// zero-init block: m_v, s_v, cnt_u, m_t, s_t, m_q, s_q (contiguous)
constexpr size_t O_MV    = O_LQ + kEQ;
constexpr size_t O_SV    = O_MV + kNT;
constexpr size_t O_CNT   = O_SV + kNT;
constexpr size_t O_MT    = O_CNT + kNQ;
constexpr size_t O_ST    = O_MT + kNT;
constexpr size_t O_MQ    = O_ST + kNT;
constexpr size_t O_SQ    = O_MQ + kNQ;
constexpr size_t O_ZEND  = O_SQ + kNQ;
constexpr size_t O_SSRC_T= O_ZEND;
constexpr size_t O_SDST_T= O_SSRC_T + kNT;
constexpr size_t O_SSRC_Q= O_SDST_T + kNT;
constexpr size_t O_SDST_Q= O_SSRC_Q + kNQ;
constexpr size_t O_QSUM  = O_SDST_Q + kNQ;
constexpr size_t O_BIAS  = O_QSUM + kD;
constexpr size_t O_TOTAL = O_BIAS + kD;

__device__ __align__(16) float g_scratch[O_TOTAL];

// monotone float->u32 key for atomicMax-based segment max
__device__ __forceinline__ unsigned fkey(float f) {
    unsigned u = __float_as_uint(f);
    return (u & 0x80000000u) ? ~u : (u | 0x80000000u);
}
__device__ __forceinline__ float funkey(unsigned u) {
    return (u & 0x80000000u) ? __uint_as_float(u & 0x7fffffffu)
                             : __uint_as_float(~u);
}

// ============================================================
// Tiled SGEMM: C[M,128] = act( [A0 | A1][M,K] @ W[K,128] + bias )
// BM=64, BK=32, 256 threads, each thread 8x4 outputs. M % 64 == 0, K % 32 == 0.
// A0 covers columns [0,K0), A1 covers [K0,K). Tiles never straddle (K0 % 32 == 0).
// act: 0 = none, 1 = ELU
// ============================================================
__global__ void sgemm_n128(const float* __restrict__ A0, const float* __restrict__ A1,
                           int K0, int K,
                           const float* __restrict__ W,
                           const float* __restrict__ bias,
                           float* __restrict__ C, int act)
{
    __shared__ float As[32][65];
    __shared__ float Bs[32][128];
    const int tid = threadIdx.x;
    const int tx = tid & 31;       // N direction (x4)
    const int ty = tid >> 5;       // M direction (x8)
    const int m0 = blockIdx.x * 64;

    float acc[8][4];
    #pragma unroll
    for (int i = 0; i < 8; i++)
        #pragma unroll
        for (int j = 0; j < 4; j++) acc[i][j] = 0.f;

    for (int kt = 0; kt < K; kt += 32) {
        const float* Ap; int ldA, kb;
        if (kt < K0) { Ap = A0; ldA = K0;      kb = kt; }
        else         { Ap = A1; ldA = K - K0;  kb = kt - K0; }

        // load A tile (64 rows x 32 cols): 512 float4, 2 per thread
        #pragma unroll
        for (int i = 0; i < 2; i++) {
            int t   = tid + i * 256;
            int row = t >> 3;
            int c4  = t & 7;
            float4 v = *reinterpret_cast<const float4*>(Ap + (size_t)(m0 + row) * ldA + kb + c4 * 4);
            As[c4*4+0][row] = v.x;
            As[c4*4+1][row] = v.y;
            As[c4*4+2][row] = v.z;
            As[c4*4+3][row] = v.w;
        }
        // load W tile (32 rows x 128 cols): 1024 float4, 4 per thread
        #pragma unroll
        for (int i = 0; i < 4; i++) {
            int t  = tid + i * 256;
            int r  = t >> 5;
            int c4 = t & 31;
            float4 v = *reinterpret_cast<const float4*>(W + (size_t)(kt + r) * 128 + c4 * 4);
            *reinterpret_cast<float4*>(&Bs[r][c4 * 4]) = v;
        }
        __syncthreads();

        #pragma unroll
        for (int k = 0; k < 32; k++) {
            float a[8], b[4];
            #pragma unroll
            for (int i = 0; i < 8; i++) a[i] = As[k][ty * 8 + i];
            #pragma unroll
            for (int j = 0; j < 4; j++) b[j] = Bs[k][tx * 4 + j];
            #pragma unroll
            for (int i = 0; i < 8; i++)
                #pragma unroll
                for (int j = 0; j < 4; j++)
                    acc[i][j] = fmaf(a[i], b[j], acc[i][j]);
        }
        __syncthreads();
    }

    float bj[4] = {0.f, 0.f, 0.f, 0.f};
    if (bias) {
        #pragma unroll
        for (int j = 0; j < 4; j++) bj[j] = bias[tx * 4 + j];
    }
    #pragma unroll
    for (int i = 0; i < 8; i++) {
        int row = m0 + ty * 8 + i;
        float4 o;
        float v0 = acc[i][0] + bj[0];
        float v1 = acc[i][1] + bj[1];
        float v2 = acc[i][2] + bj[2];
        float v3 = acc[i][3] + bj[3];
        if (act) {
            v0 = v0 > 0.f ? v0 : expm1f(v0);
            v1 = v1 > 0.f ? v1 : expm1f(v1);
            v2 = v2 > 0.f ? v2 : expm1f(v2);
            v3 = v3 > 0.f ? v3 : expm1f(v3);
        }
        o.x = v0; o.y = v1; o.z = v2; o.w = v3;
        *reinterpret_cast<float4*>(C + (size_t)row * 128 + tx * 4) = o;
    }
}

// column sums of Xq (for Q = mean(Xq, axis=0))
__global__ void colsum_kernel(const float* __restrict__ X, float* __restrict__ sums)
{
    int j  = threadIdx.x;            // 0..127
    int r0 = blockIdx.x * 128;
    float s = 0.f;
    for (int r = 0; r < 128; r++) s += X[(size_t)(r0 + r) * kD + j];
    atomicAdd(&sums[j], s);
}

// bias_eff[j] = b_mt[j] + sum_k mean_k * W_mt[256+k, j]
__global__ void bias_mt_kernel(const float* __restrict__ qsum, const float* __restrict__ W_mt,
                               const float* __restrict__ b_mt, float* __restrict__ be)
{
    int j = threadIdx.x;
    float s = b_mt[j];
    const float inv = 1.0f / (float)kNQ;
    for (int k = 0; k < kD; k++)
        s = fmaf(qsum[k] * inv, W_mt[(size_t)(256 + k) * kD + j], s);
    be[j] = s;
}

// cross logits: warp per edge, dot(Xq_ac[src], Xt_ac[dst]); track seg-max over dst + count over src
__global__ void cross_logits_kernel(const int* __restrict__ src, const int* __restrict__ dst,
                                    const float* __restrict__ Aq, const float* __restrict__ At,
                                    float* __restrict__ logits, unsigned* __restrict__ m_v,
                                    int* __restrict__ cnt_u)
{
    int idx  = blockIdx.x * blockDim.x + threadIdx.x;
    int e    = idx >> 5;
    int lane = idx & 31;
    if (e >= kEC) return;
    int u = src[e], v = dst[e];
    float4 a = *reinterpret_cast<const float4*>(Aq + (size_t)u * kD + lane * 4);
    float4 b = *reinterpret_cast<const float4*>(At + (size_t)v * kD + lane * 4);
    float p = a.x * b.x + a.y * b.y + a.z * b.z + a.w * b.w;
    #pragma unroll
    for (int o = 16; o; o >>= 1) p += __shfl_xor_sync(0xffffffffu, p, o);
    if (lane == 0) {
        logits[e] = p;
        atomicMax(&m_v[v], fkey(p));
        atomicAdd(&cnt_u[u], 1);
    }
}

// s[seg] += exp(l - m[seg])
__global__ void seg_expsum_kernel(const float* __restrict__ logits, const int* __restrict__ seg,
                                  const unsigned* __restrict__ m, float* __restrict__ s, int E)
{
    int e = blockIdx.x * blockDim.x + threadIdx.x;
    if (e >= E) return;
    int d = seg[e];
    atomicAdd(&s[d], expf(logits[e] - funkey(m[d])));
}

// Xt2q[n,:] = (cnt[n] > 0) ? Xt_vc[n,:] : 0
__global__ void fill_t2q_kernel(const int* __restrict__ cnt, const float* __restrict__ V,
                                float* __restrict__ out)
{
    size_t i = (size_t)blockIdx.x * blockDim.x + threadIdx.x;
    int n = (int)(i >> 7);
    out[i] = (cnt[n] > 0) ? V[i] : 0.f;
}

// out[seg[e],:] += softmax(e) * V[gat[e],:]   (warp per edge, vec4 red)
__global__ void seg_scatter_kernel(const float* __restrict__ logits, const int* __restrict__ gat,
                                   const int* __restrict__ seg, const unsigned* __restrict__ m,
                                   const float* __restrict__ s, const float* __restrict__ V,
                                   float* __restrict__ out, int E)
{
    int idx  = blockIdx.x * blockDim.x + threadIdx.x;
    int e    = idx >> 5;
    int lane = idx & 31;
    if (e >= E) return;
    int g = gat[e], d = seg[e];
    float a = expf(logits[e] - funkey(m[d])) / s[d];
    float4 v = *reinterpret_cast<const float4*>(V + (size_t)g * kD + lane * 4);
    float* p = out + (size_t)d * kD + lane * 4;
    asm volatile("red.global.add.v4.f32 [%0], {%1,%2,%3,%4};"
                 :: "l"(p), "f"(a * v.x), "f"(a * v.y), "f"(a * v.z), "f"(a * v.w)
                 : "memory");
}

// per-node attention scalars: ssrc[n] = H[n].Wa[0:128], sdst[n] = H[n].Wa[128:256] + ba
__global__ void node_scalars_kernel(const float* __restrict__ H, const float* __restrict__ Wa,
                                    const float* __restrict__ ba,
                                    float* __restrict__ ssrc, float* __restrict__ sdst, int N)
{
    int idx  = blockIdx.x * blockDim.x + threadIdx.x;
    int n    = idx >> 5;
    int lane = idx & 31;
    if (n >= N) return;
    float4 h  = *reinterpret_cast<const float4*>(H  + (size_t)n * kD + lane * 4);
    float4 w0 = *reinterpret_cast<const float4*>(Wa + lane * 4);
    float4 w1 = *reinterpret_cast<const float4*>(Wa + 128 + lane * 4);
    float p0 = h.x * w0.x + h.y * w0.y + h.z * w0.z + h.w * w0.w;
    float p1 = h.x * w1.x + h.y * w1.y + h.z * w1.z + h.w * w1.w;
    #pragma unroll
    for (int o = 16; o; o >>= 1) {
        p0 += __shfl_xor_sync(0xffffffffu, p0, o);
        p1 += __shfl_xor_sync(0xffffffffu, p1, o);
    }
    if (lane == 0) { ssrc[n] = p0; sdst[n] = p1 + ba[0]; }
}

// intra edge logits: l = ssrc[src] + sdst[dst]; seg-max over dst
__global__ void intra_logits_kernel(const int* __restrict__ src, const int* __restrict__ dst,
                                    const float* __restrict__ ssrc, const float* __restrict__ sdst,
                                    float* __restrict__ logits, unsigned* __restrict__ m, int E)
{
    int e = blockIdx.x * blockDim.x + threadIdx.x;
    if (e >= E) return;
    float l = ssrc[src[e]] + sdst[dst[e]];
    logits[e] = l;
    atomicMax(&m[dst[e]], fkey(l));
}

// out[n,:] = (s[n] > 0) ? Pdst[n,:] : 0   (Pdst already includes bias)
__global__ void init_out_kernel(const float* __restrict__ s, const float* __restrict__ pd,
                                float* __restrict__ out)
{
    size_t i = (size_t)blockIdx.x * blockDim.x + threadIdx.x;
    int n = (int)(i >> 7);
    out[i] = (s[n] > 0.f) ? pd[i] : 0.f;
}

// ============================================================
extern "C" void kernel_launch(void* const* d_in, const int* in_sizes, int n_in,
                              void* d_out, int out_size)
{
    (void)in_sizes; (void)n_in; (void)out_size;
    float* S = nullptr;
    cudaGetSymbolAddress((void**)&S, g_scratch);

    const float* Xq   = (const float*)d_in[0];
    const int*   eq   = (const int*)d_in[1];   // src = eq[0:EQ), dst = eq[EQ:2EQ)
    const float* Xt   = (const float*)d_in[2];
    const int*   et   = (const int*)d_in[3];
    const int*   csrc = (const int*)d_in[6];
    const int*   cdst = (const int*)d_in[7];

    const float* W_ac_q = (const float*)d_in[10]; const float* b_ac_q = (const float*)d_in[11];
    const float* W_ac_t = (const float*)d_in[12]; const float* b_ac_t = (const float*)d_in[13];
    const float* W_vc_q = (const float*)d_in[14]; const float* b_vc_q = (const float*)d_in[15];
    const float* W_vc_t = (const float*)d_in[16]; const float* b_vc_t = (const float*)d_in[17];
    const float* W_mq   = (const float*)d_in[18]; const float* b_mq   = (const float*)d_in[19];
    const float* W_mt   = (const float*)d_in[20]; const float* b_mt   = (const float*)d_in[21];
    const float* W_aq   = (const float*)d_in[22]; const float* b_aq   = (const float*)d_in[23];
    const float* W_vq   = (const float*)d_in[24]; const float* b_vq   = (const float*)d_in[25];
    const float* W_at   = (const float*)d_in[26]; const float* b_at   = (const float*)d_in[27];
    const float* W_vt   = (const float*)d_in[28]; const float* b_vt   = (const float*)d_in[29];

    float* outQ = (float*)d_out;
    float* outT = outQ + SZ;

    // zero inits (m/s/cnt block, Xq2t accumulator, column-sum accumulator)
    cudaMemsetAsync(S + O_MV,   0, (O_ZEND - O_MV) * sizeof(float), 0);
    cudaMemsetAsync(S + O_XQ2T, 0, SZ * sizeof(float), 0);
    cudaMemsetAsync(S + O_QSUM, 0, kD * sizeof(float), 0);

    const dim3 gG(kNQ / 64);  // 128 blocks for node GEMMs

    // node transforms (ELU)
    sgemm_n128<<<gG, 256>>>(Xq, nullptr, 128, 128, W_ac_q, b_ac_q, S + O_XQ_AC, 1);
    sgemm_n128<<<gG, 256>>>(Xt, nullptr, 128, 128, W_ac_t, b_ac_t, S + O_XT_AC, 1);
    sgemm_n128<<<gG, 256>>>(Xq, nullptr, 128, 128, W_vc_q, b_vc_q, S + O_XQ_VC, 1);
    sgemm_n128<<<gG, 256>>>(Xt, nullptr, 128, 128, W_vc_t, b_vc_t, S + O_XT_VC, 1);

    // Q mean folded into an effective bias for the mt GEMM
    colsum_kernel<<<kNQ / 128, 128>>>(Xq, S + O_QSUM);
    bias_mt_kernel<<<1, 128>>>(S + O_QSUM, W_mt, b_mt, S + O_BIAS);

    // cross attention
    cross_logits_kernel<<<(kEC * 32) / 256, 256>>>(csrc, cdst, S + O_XQ_AC, S + O_XT_AC,
                                                   S + O_LC, (unsigned*)(S + O_MV), (int*)(S + O_CNT));
    seg_expsum_kernel<<<kEC / 256, 256>>>(S + O_LC, cdst, (unsigned*)(S + O_MV), S + O_SV, kEC);
    // t2q is degenerate: softmax sums to 1 within a segment, values constant per segment
    fill_t2q_kernel<<<SZ / 256, 256>>>((int*)(S + O_CNT), S + O_XT_VC, S + O_XT2Q);
    // q2t: real softmax scatter (gather by src, scatter to dst)
    seg_scatter_kernel<<<(kEC * 32) / 256, 256>>>(S + O_LC, csrc, cdst, (unsigned*)(S + O_MV),
                                                  S + O_SV, S + O_XQ_VC, S + O_XQ2T, kEC);

    // merged features
    sgemm_n128<<<gG, 256>>>(Xq, S + O_XT2Q, 128, 256, W_mq, b_mq,     S + O_XQM, 0);
    sgemm_n128<<<gG, 256>>>(Xt, S + O_XQ2T, 128, 256, W_mt, S + O_BIAS, S + O_XTM, 0);

    // intra-graph: factor edge GEMMs into per-node projections
    sgemm_n128<<<gG, 256>>>(S + O_XTM, nullptr, 128, 128, W_vt,            nullptr, S + O_PS_T, 0);
    sgemm_n128<<<gG, 256>>>(S + O_XTM, nullptr, 128, 128, W_vt + 128 * kD, b_vt,    S + O_PD_T, 0);
    sgemm_n128<<<gG, 256>>>(S + O_XQM, nullptr, 128, 128, W_vq,            nullptr, S + O_PS_Q, 0);
    sgemm_n128<<<gG, 256>>>(S + O_XQM, nullptr, 128, 128, W_vq + 128 * kD, b_vq,    S + O_PD_Q, 0);

    node_scalars_kernel<<<(kNT * 32) / 256, 256>>>(S + O_XTM, W_at, b_at, S + O_SSRC_T, S + O_SDST_T, kNT);
    node_scalars_kernel<<<(kNQ * 32) / 256, 256>>>(S + O_XQM, W_aq, b_aq, S + O_SSRC_Q, S + O_SDST_Q, kNQ);

    intra_logits_kernel<<<kET / 256, 256>>>(et, et + kET, S + O_SSRC_T, S + O_SDST_T,
                                            S + O_LT, (unsigned*)(S + O_MT), kET);
    intra_logits_kernel<<<kEQ / 256, 256>>>(eq, eq + kEQ, S + O_SSRC_Q, S + O_SDST_Q,
                                            S + O_LQ, (unsigned*)(S + O_MQ), kEQ);
    seg_expsum_kernel<<<kET / 256, 256>>>(S + O_LT, et + kET, (unsigned*)(S + O_MT), S + O_ST, kET);
    seg_expsum_kernel<<<kEQ / 256, 256>>>(S + O_LQ, eq + kEQ, (unsigned*)(S + O_MQ), S + O_SQ, kEQ);

    // out[n] = (deg>0 ? Pdst[n]+b : 0) + sum_e softmax * Psrc[src_e]  (softmax sums to 1)
    init_out_kernel<<<SZ / 256, 256>>>(S + O_ST, S + O_PD_T, outT);
    init_out_kernel<<<SZ / 256, 256>>>(S + O_SQ, S + O_PD_Q, outQ);
    seg_scatter_kernel<<<(kET * 32) / 256, 256>>>(S + O_LT, et, et + kET, (unsigned*)(S + O_MT),
                                                  S + O_ST, S + O_PS_T, outT, kET);
    seg_scatter_kernel<<<(kEQ * 32) / 256, 256>>>(S + O_LQ, eq, eq + kEQ, (unsigned*)(S + O_MQ),
                                                  S + O_SQ, S + O_PS_Q, outQ, kEQ);
}

// round 2
// speedup vs baseline: 1.0024x; 1.0024x over previous
#include <cuda_runtime.h>
#include <math.h>

// Problem constants
constexpr int kNQ = 8192;
constexpr int kNT = 8192;
constexpr int kD  = 128;
constexpr int kEC = 262144;
constexpr int kEQ = 262144;
constexpr int kET = 262144;

constexpr size_t SZ = (size_t)kNQ * kD;   // 1,048,576 floats per node matrix

// ---- scratch layout (floats) ----
constexpr size_t O_XQ_AC = 0;
constexpr size_t O_XT_AC = 1*SZ;
constexpr size_t O_XQ_VC = 2*SZ;
constexpr size_t O_XT_VC = 3*SZ;
constexpr size_t O_XT2Q  = 4*SZ;
constexpr size_t O_XQ2T  = 5*SZ;
constexpr size_t O_XQM   = 6*SZ;
constexpr size_t O_XTM   = 7*SZ;
constexpr size_t O_PS_T  = 8*SZ;
constexpr size_t O_PD_T  = 9*SZ;
constexpr size_t O_PS_Q  = 10*SZ;
constexpr size_t O_PD_Q  = 11*SZ;
constexpr size_t O_LC    = 12*SZ;
constexpr size_t O_LT    = O_LC + kEC;
constexpr size_t O_LQ    = O_LT + kET;
// zero-init block: m_v, s_v, cnt_u, m_t, s_t, m_q, s_q (contiguous)
constexpr size_t O_MV    = O_LQ + kEQ;
constexpr size_t O_SV    = O_MV + kNT;
constexpr size_t O_CNT   = O_SV + kNT;
constexpr size_t O_MT    = O_CNT + kNQ;
constexpr size_t O_ST    = O_MT + kNT;
constexpr size_t O_MQ    = O_ST + kNT;
constexpr size_t O_SQ    = O_MQ + kNQ;
constexpr size_t O_ZEND  = O_SQ + kNQ;
constexpr size_t O_SSRC_T= O_ZEND;
constexpr size_t O_SDST_T= O_SSRC_T + kNT;
constexpr size_t O_SSRC_Q= O_SDST_T + kNT;
constexpr size_t O_SDST_Q= O_SSRC_Q + kNQ;
constexpr size_t O_QSUM  = O_SDST_Q + kNQ;
constexpr size_t O_BIAS  = O_QSUM + kD;
constexpr size_t O_TOTAL = O_BIAS + kD;

__device__ __align__(16) float g_scratch[O_TOTAL];

// monotone float->u32 key for atomicMax-based segment max
__device__ __forceinline__ unsigned fkey(float f) {
    unsigned u = __float_as_uint(f);
    return (u & 0x80000000u) ? ~u : (u | 0x80000000u);
}
__device__ __forceinline__ float funkey(unsigned u) {
    return (u & 0x80000000u) ? __uint_as_float(u & 0x7fffffffu)
                             : __uint_as_float(~u);
}

// ============================================================
// Tiled SGEMM: C[M,128] = act( [A0 | A1][M,K] @ W[K,128] + bias )
// BM=64, BK=32, 256 threads, each thread 8x4 outputs. M % 64 == 0, K % 32 == 0.
// A0 covers columns [0,K0), A1 covers [K0,K). Tiles never straddle (K0 % 32 == 0).
// act: 0 = none, 1 = ELU
// ============================================================
__global__ void sgemm_n128(const float* __restrict__ A0, const float* __restrict__ A1,
                           int K0, int K,
                           const float* __restrict__ W,
                           const float* __restrict__ bias,
                           float* __restrict__ C, int act)
{
    __shared__ float As[32][65];
    __shared__ float Bs[32][128];
    const int tid = threadIdx.x;
    const int tx = tid & 31;       // N direction (x4)
    const int ty = tid >> 5;       // M direction (x8)
    const int m0 = blockIdx.x * 64;

    float acc[8][4];
    #pragma unroll
    for (int i = 0; i < 8; i++)
        #pragma unroll
        for (int j = 0; j < 4; j++) acc[i][j] = 0.f;

    for (int kt = 0; kt < K; kt += 32) {
        const float* Ap; int ldA, kb;
        if (kt < K0) { Ap = A0; ldA = K0;      kb = kt; }
        else         { Ap = A1; ldA = K - K0;  kb = kt - K0; }

        // load A tile (64 rows x 32 cols): 512 float4, 2 per thread
        #pragma unroll
        for (int i = 0; i < 2; i++) {
            int t   = tid + i * 256;
            int row = t >> 3;
            int c4  = t & 7;
            float4 v = *reinterpret_cast<const float4*>(Ap + (size_t)(m0 + row) * ldA + kb + c4 * 4);
            As[c4*4+0][row] = v.x;
            As[c4*4+1][row] = v.y;
            As[c4*4+2][row] = v.z;
            As[c4*4+3][row] = v.w;
        }
        // load W tile (32 rows x 128 cols): 1024 float4, 4 per thread
        #pragma unroll
        for (int i = 0; i < 4; i++) {
            int t  = tid + i * 256;
            int r  = t >> 5;
            int c4 = t & 31;
            float4 v = *reinterpret_cast<const float4*>(W + (size_t)(kt + r) * 128 + c4 * 4);
            *reinterpret_cast<float4*>(&Bs[r][c4 * 4]) = v;
        }
        __syncthreads();

        #pragma unroll
        for (int k = 0; k < 32; k++) {
            float a[8], b[4];
            #pragma unroll
            for (int i = 0; i < 8; i++) a[i] = As[k][ty * 8 + i];
            #pragma unroll
            for (int j = 0; j < 4; j++) b[j] = Bs[k][tx * 4 + j];
            #pragma unroll
            for (int i = 0; i < 8; i++)
                #pragma unroll
                for (int j = 0; j < 4; j++)
                    acc[i][j] = fmaf(a[i], b[j], acc[i][j]);
        }
        __syncthreads();
    }

    float bj[4] = {0.f, 0.f, 0.f, 0.f};
    if (bias) {
        #pragma unroll
        for (int j = 0; j < 4; j++) bj[j] = bias[tx * 4 + j];
    }
    #pragma unroll
    for (int i = 0; i < 8; i++) {
        int row = m0 + ty * 8 + i;
        float4 o;
        float v0 = acc[i][0] + bj[0];
        float v1 = acc[i][1] + bj[1];
        float v2 = acc[i][2] + bj[2];
        float v3 = acc[i][3] + bj[3];
        if (act) {
            v0 = v0 > 0.f ? v0 : expm1f(v0);
            v1 = v1 > 0.f ? v1 : expm1f(v1);
            v2 = v2 > 0.f ? v2 : expm1f(v2);
            v3 = v3 > 0.f ? v3 : expm1f(v3);
        }
        o.x = v0; o.y = v1; o.z = v2; o.w = v3;
        *reinterpret_cast<float4*>(C + (size_t)row * 128 + tx * 4) = o;
    }
}

// column sums of Xq (for Q = mean(Xq, axis=0))
__global__ void colsum_kernel(const float* __restrict__ X, float* __restrict__ sums)
{
    int j  = threadIdx.x;            // 0..127
    int r0 = blockIdx.x * 128;
    float s = 0.f;
    for (int r = 0; r < 128; r++) s += X[(size_t)(r0 + r) * kD + j];
    atomicAdd(&sums[j], s);
}

// bias_eff[j] = b_mt[j] + sum_k mean_k * W_mt[256+k, j]
__global__ void bias_mt_kernel(const float* __restrict__ qsum, const float* __restrict__ W_mt,
                               const float* __restrict__ b_mt, float* __restrict__ be)
{
    int j = threadIdx.x;
    float s = b_mt[j];
    const float inv = 1.0f / (float)kNQ;
    for (int k = 0; k < kD; k++)
        s = fmaf(qsum[k] * inv, W_mt[(size_t)(256 + k) * kD + j], s);
    be[j] = s;
}

// cross logits: warp per edge, dot(Xq_ac[src], Xt_ac[dst]); track seg-max over dst + count over src
__global__ void cross_logits_kernel(const int* __restrict__ src, const int* __restrict__ dst,
                                    const float* __restrict__ Aq, const float* __restrict__ At,
                                    float* __restrict__ logits, unsigned* __restrict__ m_v,
                                    int* __restrict__ cnt_u)
{
    int idx  = blockIdx.x * blockDim.x + threadIdx.x;
    int e    = idx >> 5;
    int lane = idx & 31;
    if (e >= kEC) return;
    int u = src[e], v = dst[e];
    float4 a = *reinterpret_cast<const float4*>(Aq + (size_t)u * kD + lane * 4);
    float4 b = *reinterpret_cast<const float4*>(At + (size_t)v * kD + lane * 4);
    float p = a.x * b.x + a.y * b.y + a.z * b.z + a.w * b.w;
    #pragma unroll
    for (int o = 16; o; o >>= 1) p += __shfl_xor_sync(0xffffffffu, p, o);
    if (lane == 0) {
        logits[e] = p;
        atomicMax(&m_v[v], fkey(p));
        atomicAdd(&cnt_u[u], 1);
    }
}

// s[seg] += exp(l - m[seg])
__global__ void seg_expsum_kernel(const float* __restrict__ logits, const int* __restrict__ seg,
                                  const unsigned* __restrict__ m, float* __restrict__ s, int E)
{
    int e = blockIdx.x * blockDim.x + threadIdx.x;
    if (e >= E) return;
    int d = seg[e];
    atomicAdd(&s[d], expf(logits[e] - funkey(m[d])));
}

// Xt2q[n,:] = (cnt[n] > 0) ? Xt_vc[n,:] : 0
__global__ void fill_t2q_kernel(const int* __restrict__ cnt, const float* __restrict__ V,
                                float* __restrict__ out)
{
    size_t i = (size_t)blockIdx.x * blockDim.x + threadIdx.x;
    int n = (int)(i >> 7);
    out[i] = (cnt[n] > 0) ? V[i] : 0.f;
}

// out[seg[e],:] += softmax(e) * V[gat[e],:]   (warp per edge, vec4 red)
__global__ void seg_scatter_kernel(const float* __restrict__ logits, const int* __restrict__ gat,
                                   const int* __restrict__ seg, const unsigned* __restrict__ m,
                                   const float* __restrict__ s, const float* __restrict__ V,
                                   float* __restrict__ out, int E)
{
    int idx  = blockIdx.x * blockDim.x + threadIdx.x;
    int e    = idx >> 5;
    int lane = idx & 31;
    if (e >= E) return;
    int g = gat[e], d = seg[e];
    float a = expf(logits[e] - funkey(m[d])) / s[d];
    float4 v = *reinterpret_cast<const float4*>(V + (size_t)g * kD + lane * 4);
    float* p = out + (size_t)d * kD + lane * 4;
    asm volatile("red.global.add.v4.f32 [%0], {%1,%2,%3,%4};"
                 :: "l"(p), "f"(a * v.x), "f"(a * v.y), "f"(a * v.z), "f"(a * v.w)
                 : "memory");
}

// per-node attention scalars: ssrc[n] = H[n].Wa[0:128], sdst[n] = H[n].Wa[128:256] + ba
__global__ void node_scalars_kernel(const float* __restrict__ H, const float* __restrict__ Wa,
                                    const float* __restrict__ ba,
                                    float* __restrict__ ssrc, float* __restrict__ sdst, int N)
{
    int idx  = blockIdx.x * blockDim.x + threadIdx.x;
    int n    = idx >> 5;
    int lane = idx & 31;
    if (n >= N) return;
    float4 h  = *reinterpret_cast<const float4*>(H  + (size_t)n * kD + lane * 4);
    float4 w0 = *reinterpret_cast<const float4*>(Wa + lane * 4);
    float4 w1 = *reinterpret_cast<const float4*>(Wa + 128 + lane * 4);
    float p0 = h.x * w0.x + h.y * w0.y + h.z * w0.z + h.w * w0.w;
    float p1 = h.x * w1.x + h.y * w1.y + h.z * w1.z + h.w * w1.w;
    #pragma unroll
    for (int o = 16; o; o >>= 1) {
        p0 += __shfl_xor_sync(0xffffffffu, p0, o);
        p1 += __shfl_xor_sync(0xffffffffu, p1, o);
    }
    if (lane == 0) { ssrc[n] = p0; sdst[n] = p1 + ba[0]; }
}

// intra edge logits: l = ssrc[src] + sdst[dst]; seg-max over dst
__global__ void intra_logits_kernel(const int* __restrict__ src, const int* __restrict__ dst,
                                    const float* __restrict__ ssrc, const float* __restrict__ sdst,
                                    float* __restrict__ logits, unsigned* __restrict__ m, int E)
{
    int e = blockIdx.x * blockDim.x + threadIdx.x;
    if (e >= E) return;
    float l = ssrc[src[e]] + sdst[dst[e]];
    logits[e] = l;
    atomicMax(&m[dst[e]], fkey(l));
}

// out[n,:] = (s[n] > 0) ? Pdst[n,:] : 0   (Pdst already includes bias)
__global__ void init_out_kernel(const float* __restrict__ s, const float* __restrict__ pd,
                                float* __restrict__ out)
{
    size_t i = (size_t)blockIdx.x * blockDim.x + threadIdx.x;
    int n = (int)(i >> 7);
    out[i] = (s[n] > 0.f) ? pd[i] : 0.f;
}

// ============================================================
extern "C" void kernel_launch(void* const* d_in, const int* in_sizes, int n_in,
                              void* d_out, int out_size)
{
    (void)in_sizes; (void)n_in; (void)out_size;
    float* S = nullptr;
    cudaGetSymbolAddress((void**)&S, g_scratch);

    const float* Xq   = (const float*)d_in[0];
    const int*   eq   = (const int*)d_in[1];   // src = eq[0:EQ), dst = eq[EQ:2EQ)
    const float* Xt   = (const float*)d_in[2];
    const int*   et   = (const int*)d_in[3];
    const int*   csrc = (const int*)d_in[6];
    const int*   cdst = (const int*)d_in[7];

    const float* W_ac_q = (const float*)d_in[10]; const float* b_ac_q = (const float*)d_in[11];
    const float* W_ac_t = (const float*)d_in[12]; const float* b_ac_t = (const float*)d_in[13];
    const float* W_vc_q = (const float*)d_in[14]; const float* b_vc_q = (const float*)d_in[15];
    const float* W_vc_t = (const float*)d_in[16]; const float* b_vc_t = (const float*)d_in[17];
    const float* W_mq   = (const float*)d_in[18]; const float* b_mq   = (const float*)d_in[19];
    const float* W_mt   = (const float*)d_in[20]; const float* b_mt   = (const float*)d_in[21];
    const float* W_aq   = (const float*)d_in[22]; const float* b_aq   = (const float*)d_in[23];
    const float* W_vq   = (const float*)d_in[24]; const float* b_vq   = (const float*)d_in[25];
    const float* W_at   = (const float*)d_in[26]; const float* b_at   = (const float*)d_in[27];
    const float* W_vt   = (const float*)d_in[28]; const float* b_vt   = (const float*)d_in[29];

    float* outQ = (float*)d_out;
    float* outT = outQ + SZ;

    // zero inits (m/s/cnt block, Xq2t accumulator, column-sum accumulator)
    cudaMemsetAsync(S + O_MV,   0, (O_ZEND - O_MV) * sizeof(float), 0);
    cudaMemsetAsync(S + O_XQ2T, 0, SZ * sizeof(float), 0);
    cudaMemsetAsync(S + O_QSUM, 0, kD * sizeof(float), 0);

    const dim3 gG(kNQ / 64);  // 128 blocks for node GEMMs

    // node transforms (ELU)
    sgemm_n128<<<gG, 256>>>(Xq, nullptr, 128, 128, W_ac_q, b_ac_q, S + O_XQ_AC, 1);
    sgemm_n128<<<gG, 256>>>(Xt, nullptr, 128, 128, W_ac_t, b_ac_t, S + O_XT_AC, 1);
    sgemm_n128<<<gG, 256>>>(Xq, nullptr, 128, 128, W_vc_q, b_vc_q, S + O_XQ_VC, 1);
    sgemm_n128<<<gG, 256>>>(Xt, nullptr, 128, 128, W_vc_t, b_vc_t, S + O_XT_VC, 1);

    // Q mean folded into an effective bias for the mt GEMM
    colsum_kernel<<<kNQ / 128, 128>>>(Xq, S + O_QSUM);
    bias_mt_kernel<<<1, 128>>>(S + O_QSUM, W_mt, b_mt, S + O_BIAS);

    // cross attention
    cross_logits_kernel<<<(kEC * 32) / 256, 256>>>(csrc, cdst, S + O_XQ_AC, S + O_XT_AC,
                                                   S + O_LC, (unsigned*)(S + O_MV), (int*)(S + O_CNT));
    seg_expsum_kernel<<<kEC / 256, 256>>>(S + O_LC, cdst, (unsigned*)(S + O_MV), S + O_SV, kEC);
    // t2q is degenerate: softmax sums to 1 within a segment, values constant per segment
    fill_t2q_kernel<<<SZ / 256, 256>>>((int*)(S + O_CNT), S + O_XT_VC, S + O_XT2Q);
    // q2t: real softmax scatter (gather by src, scatter to dst)
    seg_scatter_kernel<<<(kEC * 32) / 256, 256>>>(S + O_LC, csrc, cdst, (unsigned*)(S + O_MV),
                                                  S + O_SV, S + O_XQ_VC, S + O_XQ2T, kEC);

    // merged features
    sgemm_n128<<<gG, 256>>>(Xq, S + O_XT2Q, 128, 256, W_mq, b_mq,     S + O_XQM, 0);
    sgemm_n128<<<gG, 256>>>(Xt, S + O_XQ2T, 128, 256, W_mt, S + O_BIAS, S + O_XTM, 0);

    // intra-graph: factor edge GEMMs into per-node projections
    sgemm_n128<<<gG, 256>>>(S + O_XTM, nullptr, 128, 128, W_vt,            nullptr, S + O_PS_T, 0);
    sgemm_n128<<<gG, 256>>>(S + O_XTM, nullptr, 128, 128, W_vt + 128 * kD, b_vt,    S + O_PD_T, 0);
    sgemm_n128<<<gG, 256>>>(S + O_XQM, nullptr, 128, 128, W_vq,            nullptr, S + O_PS_Q, 0);
    sgemm_n128<<<gG, 256>>>(S + O_XQM, nullptr, 128, 128, W_vq + 128 * kD, b_vq,    S + O_PD_Q, 0);

    node_scalars_kernel<<<(kNT * 32) / 256, 256>>>(S + O_XTM, W_at, b_at, S + O_SSRC_T, S + O_SDST_T, kNT);
    node_scalars_kernel<<<(kNQ * 32) / 256, 256>>>(S + O_XQM, W_aq, b_aq, S + O_SSRC_Q, S + O_SDST_Q, kNQ);

    intra_logits_kernel<<<kET / 256, 256>>>(et, et + kET, S + O_SSRC_T, S + O_SDST_T,
                                            S + O_LT, (unsigned*)(S + O_MT), kET);
    intra_logits_kernel<<<kEQ / 256, 256>>>(eq, eq + kEQ, S + O_SSRC_Q, S + O_SDST_Q,
                                            S + O_LQ, (unsigned*)(S + O_MQ), kEQ);
    seg_expsum_kernel<<<kET / 256, 256>>>(S + O_LT, et + kET, (unsigned*)(S + O_MT), S + O_ST, kET);
    seg_expsum_kernel<<<kEQ / 256, 256>>>(S + O_LQ, eq + kEQ, (unsigned*)(S + O_MQ), S + O_SQ, kEQ);

    // out[n] = (deg>0 ? Pdst[n]+b : 0) + sum_e softmax * Psrc[src_e]  (softmax sums to 1)
    init_out_kernel<<<SZ / 256, 256>>>(S + O_ST, S + O_PD_T, outT);
    init_out_kernel<<<SZ / 256, 256>>>(S + O_SQ, S + O_PD_Q, outQ);
    seg_scatter_kernel<<<(kET * 32) / 256, 256>>>(S + O_LT, et, et + kET, (unsigned*)(S + O_MT),
                                                  S + O_ST, S + O_PS_T, outT, kET);
    seg_scatter_kernel<<<(kEQ * 32) / 256, 256>>>(S + O_LQ, eq, eq + kEQ, (unsigned*)(S + O_MQ),
                                                  S + O_SQ, S + O_PS_Q, outQ, kEQ);
}

// round 3
// speedup vs baseline: 1.1643x; 1.1615x over previous
#include <cuda_runtime.h>
#include <math.h>

// Problem constants
constexpr int kNQ = 8192;
constexpr int kNT = 8192;
constexpr int kD  = 128;
constexpr int kEC = 262144;
constexpr int kEQ = 262144;
constexpr int kET = 262144;

constexpr size_t SZ = (size_t)kNQ * kD;

// ---- scratch layout (floats) ----
constexpr size_t O_XQ_AC = 0;
constexpr size_t O_XT_AC = 1*SZ;
constexpr size_t O_XQ_VC = 2*SZ;
constexpr size_t O_XT_VC = 3*SZ;
constexpr size_t O_XT2Q  = 4*SZ;
constexpr size_t O_XQ2T  = 5*SZ;
constexpr size_t O_XQM   = 6*SZ;
constexpr size_t O_XTM   = 7*SZ;
constexpr size_t O_PS_T  = 8*SZ;
constexpr size_t O_PD_T  = 9*SZ;
constexpr size_t O_PS_Q  = 10*SZ;
constexpr size_t O_PD_Q  = 11*SZ;
constexpr size_t O_LC    = 12*SZ;
constexpr size_t O_LT    = O_LC + kEC;
constexpr size_t O_LQ    = O_LT + kET;
constexpr size_t O_MV    = O_LQ + kEQ;   // zero-init block start
constexpr size_t O_SV    = O_MV + kNT;
constexpr size_t O_CNT   = O_SV + kNT;
constexpr size_t O_MT    = O_CNT + kNQ;
constexpr size_t O_ST    = O_MT + kNT;
constexpr size_t O_MQ    = O_ST + kNT;
constexpr size_t O_SQ    = O_MQ + kNQ;
constexpr size_t O_ZEND  = O_SQ + kNQ;
constexpr size_t O_SSRC_T= O_ZEND;
constexpr size_t O_SDST_T= O_SSRC_T + kNT;
constexpr size_t O_SSRC_Q= O_SDST_T + kNT;
constexpr size_t O_SDST_Q= O_SSRC_Q + kNQ;
constexpr size_t O_QSUM  = O_SDST_Q + kNQ;
constexpr size_t O_BIAS  = O_QSUM + kD;
constexpr size_t O_TOTAL = O_BIAS + kD;

__device__ __align__(16) float g_scratch[O_TOTAL];

__device__ __forceinline__ unsigned fkey(float f) {
    unsigned u = __float_as_uint(f);
    return (u & 0x80000000u) ? ~u : (u | 0x80000000u);
}
__device__ __forceinline__ float funkey(unsigned u) {
    return (u & 0x80000000u) ? __uint_as_float(u & 0x7fffffffu)
                             : __uint_as_float(~u);
}

// ============================================================
// Batched tiled SGEMM. Up to 4 jobs per launch (blockIdx.y selects).
// C[M,128] = act( [A0|A1][M,K] @ W[K,128] + bias ), BM=64, BK=32,
// 256 thr, 8x4 outputs per thread.
// ============================================================
struct GemmJob {
    const float* A0; const float* A1;
    int K0; int K;
    const float* W; const float* bias;
    float* C; int act;
};
struct GemmBatch { GemmJob j[4]; };

__global__ void sgemm_n128_b(const __grid_constant__ GemmBatch batch)
{
    const GemmJob& J = batch.j[blockIdx.y];

    __shared__ float As[32][65];
    __shared__ float Bs[32][128];
    const int tid = threadIdx.x;
    const int tx = tid & 31;
    const int ty = tid >> 5;
    const int m0 = blockIdx.x * 64;

    float acc[8][4];
    #pragma unroll
    for (int i = 0; i < 8; i++)
        #pragma unroll
        for (int j = 0; j < 4; j++) acc[i][j] = 0.f;

    const int K = J.K, K0 = J.K0;
    for (int kt = 0; kt < K; kt += 32) {
        const float* Ap; int ldA, kb;
        if (kt < K0) { Ap = J.A0; ldA = K0;     kb = kt; }
        else         { Ap = J.A1; ldA = K - K0; kb = kt - K0; }

        #pragma unroll
        for (int i = 0; i < 2; i++) {
            int t   = tid + i * 256;
            int row = t >> 3;
            int c4  = t & 7;
            float4 v = *reinterpret_cast<const float4*>(Ap + (size_t)(m0 + row) * ldA + kb + c4 * 4);
            As[c4*4+0][row] = v.x;
            As[c4*4+1][row] = v.y;
            As[c4*4+2][row] = v.z;
            As[c4*4+3][row] = v.w;
        }
        #pragma unroll
        for (int i = 0; i < 4; i++) {
            int t  = tid + i * 256;
            int r  = t >> 5;
            int c4 = t & 31;
            float4 v = *reinterpret_cast<const float4*>(J.W + (size_t)(kt + r) * 128 + c4 * 4);
            *reinterpret_cast<float4*>(&Bs[r][c4 * 4]) = v;
        }
        __syncthreads();

        #pragma unroll
        for (int k = 0; k < 32; k++) {
            float a[8], b[4];
            #pragma unroll
            for (int i = 0; i < 8; i++) a[i] = As[k][ty * 8 + i];
            #pragma unroll
            for (int j = 0; j < 4; j++) b[j] = Bs[k][tx * 4 + j];
            #pragma unroll
            for (int i = 0; i < 8; i++)
                #pragma unroll
                for (int j = 0; j < 4; j++)
                    acc[i][j] = fmaf(a[i], b[j], acc[i][j]);
        }
        __syncthreads();
    }

    float bj[4] = {0.f, 0.f, 0.f, 0.f};
    if (J.bias) {
        #pragma unroll
        for (int j = 0; j < 4; j++) bj[j] = J.bias[tx * 4 + j];
    }
    const int act = J.act;
    #pragma unroll
    for (int i = 0; i < 8; i++) {
        int row = m0 + ty * 8 + i;
        float v0 = acc[i][0] + bj[0];
        float v1 = acc[i][1] + bj[1];
        float v2 = acc[i][2] + bj[2];
        float v3 = acc[i][3] + bj[3];
        if (act) {
            v0 = v0 > 0.f ? v0 : expm1f(v0);
            v1 = v1 > 0.f ? v1 : expm1f(v1);
            v2 = v2 > 0.f ? v2 : expm1f(v2);
            v3 = v3 > 0.f ? v3 : expm1f(v3);
        }
        float4 o = {v0, v1, v2, v3};
        *reinterpret_cast<float4*>(J.C + (size_t)row * 128 + tx * 4) = o;
    }
}

// column sums of Xq (for Q = mean(Xq, axis=0))
__global__ void colsum_kernel(const float* __restrict__ X, float* __restrict__ sums)
{
    int j  = threadIdx.x;
    int r0 = blockIdx.x * 128;
    float s = 0.f;
    for (int r = 0; r < 128; r++) s += X[(size_t)(r0 + r) * kD + j];
    atomicAdd(&sums[j], s);
}

__global__ void bias_mt_kernel(const float* __restrict__ qsum, const float* __restrict__ W_mt,
                               const float* __restrict__ b_mt, float* __restrict__ be)
{
    int j = threadIdx.x;
    float s = b_mt[j];
    const float inv = 1.0f / (float)kNQ;
    for (int k = 0; k < kD; k++)
        s = fmaf(qsum[k] * inv, W_mt[(size_t)(256 + k) * kD + j], s);
    be[j] = s;
}

// cross logits: warp per edge
__global__ void cross_logits_kernel(const int* __restrict__ src, const int* __restrict__ dst,
                                    const float* __restrict__ Aq, const float* __restrict__ At,
                                    float* __restrict__ logits, unsigned* __restrict__ m_v,
                                    int* __restrict__ cnt_u)
{
    int idx  = blockIdx.x * blockDim.x + threadIdx.x;
    int e    = idx >> 5;
    int lane = idx & 31;
    if (e >= kEC) return;
    int u = src[e], v = dst[e];
    float4 a = *reinterpret_cast<const float4*>(Aq + (size_t)u * kD + lane * 4);
    float4 b = *reinterpret_cast<const float4*>(At + (size_t)v * kD + lane * 4);
    float p = a.x * b.x + a.y * b.y + a.z * b.z + a.w * b.w;
    #pragma unroll
    for (int o = 16; o; o >>= 1) p += __shfl_xor_sync(0xffffffffu, p, o);
    if (lane == 0) {
        logits[e] = p;
        atomicMax(&m_v[v], fkey(p));
        atomicAdd(&cnt_u[u], 1);
    }
}

// batched s[seg] += exp(l - m[seg])  (blockIdx.y selects set; gridDim.y may be 1 or 2)
struct ExpJob { const float* logits; const int* seg; const unsigned* m; float* s; };
struct ExpBatch { ExpJob j[2]; };
__global__ void seg_expsum_b(const __grid_constant__ ExpBatch batch, int E)
{
    const ExpJob& J = batch.j[blockIdx.y];
    int e = blockIdx.x * blockDim.x + threadIdx.x;
    if (e >= E) return;
    int d = J.seg[e];
    atomicAdd(&J.s[d], expf(J.logits[e] - funkey(J.m[d])));
}

__global__ void fill_t2q_kernel(const int* __restrict__ cnt, const float* __restrict__ V,
                                float* __restrict__ out)
{
    size_t i = (size_t)blockIdx.x * blockDim.x + threadIdx.x;
    int n = (int)(i >> 7);
    out[i] = (cnt[n] > 0) ? V[i] : 0.f;
}

// batched softmax scatter: out[seg,:] += a * V[gat,:], warp per edge
struct ScatJob {
    const float* logits; const int* gat; const int* seg;
    const unsigned* m; const float* s; const float* V; float* out;
};
struct ScatBatch { ScatJob j[2]; };
__global__ void seg_scatter_b(const __grid_constant__ ScatBatch batch, int E)
{
    const ScatJob& J = batch.j[blockIdx.y];
    int idx  = blockIdx.x * blockDim.x + threadIdx.x;
    int e    = idx >> 5;
    int lane = idx & 31;
    if (e >= E) return;
    int g = J.gat[e], d = J.seg[e];
    float a = expf(J.logits[e] - funkey(J.m[d])) / J.s[d];
    float4 v = *reinterpret_cast<const float4*>(J.V + (size_t)g * kD + lane * 4);
    float* p = J.out + (size_t)d * kD + lane * 4;
    asm volatile("red.global.add.v4.f32 [%0], {%1,%2,%3,%4};"
                 :: "l"(p), "f"(a * v.x), "f"(a * v.y), "f"(a * v.z), "f"(a * v.w)
                 : "memory");
}

// batched per-node attention scalars
struct NsJob { const float* H; const float* Wa; const float* ba; float* ssrc; float* sdst; };
struct NsBatch { NsJob j[2]; };
__global__ void node_scalars_b(const __grid_constant__ NsBatch batch, int N)
{
    const NsJob& J = batch.j[blockIdx.y];
    int idx  = blockIdx.x * blockDim.x + threadIdx.x;
    int n    = idx >> 5;
    int lane = idx & 31;
    if (n >= N) return;
    float4 h  = *reinterpret_cast<const float4*>(J.H  + (size_t)n * kD + lane * 4);
    float4 w0 = *reinterpret_cast<const float4*>(J.Wa + lane * 4);
    float4 w1 = *reinterpret_cast<const float4*>(J.Wa + 128 + lane * 4);
    float p0 = h.x * w0.x + h.y * w0.y + h.z * w0.z + h.w * w0.w;
    float p1 = h.x * w1.x + h.y * w1.y + h.z * w1.z + h.w * w1.w;
    #pragma unroll
    for (int o = 16; o; o >>= 1) {
        p0 += __shfl_xor_sync(0xffffffffu, p0, o);
        p1 += __shfl_xor_sync(0xffffffffu, p1, o);
    }
    if (lane == 0) { J.ssrc[n] = p0; J.sdst[n] = p1 + J.ba[0]; }
}

// batched intra edge logits
struct IlJob { const int* src; const int* dst; const float* ssrc; const float* sdst;
               float* logits; unsigned* m; };
struct IlBatch { IlJob j[2]; };
__global__ void intra_logits_b(const __grid_constant__ IlBatch batch, int E)
{
    const IlJob& J = batch.j[blockIdx.y];
    int e = blockIdx.x * blockDim.x + threadIdx.x;
    if (e >= E) return;
    float l = J.ssrc[J.src[e]] + J.sdst[J.dst[e]];
    J.logits[e] = l;
    atomicMax(&J.m[J.dst[e]], fkey(l));
}

// batched: out[n,:] = (s[n] > 0) ? Pdst[n,:] : 0
struct IoJob { const float* s; const float* pd; float* out; };
struct IoBatch { IoJob j[2]; };
__global__ void init_out_b(const __grid_constant__ IoBatch batch)
{
    const IoJob& J = batch.j[blockIdx.y];
    size_t i = (size_t)blockIdx.x * blockDim.x + threadIdx.x;
    int n = (int)(i >> 7);
    J.out[i] = (J.s[n] > 0.f) ? J.pd[i] : 0.f;
}

// ============================================================
extern "C" void kernel_launch(void* const* d_in, const int* in_sizes, int n_in,
                              void* d_out, int out_size)
{
    (void)in_sizes; (void)n_in; (void)out_size;
    float* S = nullptr;
    cudaGetSymbolAddress((void**)&S, g_scratch);

    const float* Xq   = (const float*)d_in[0];
    const int*   eq   = (const int*)d_in[1];
    const float* Xt   = (const float*)d_in[2];
    const int*   et   = (const int*)d_in[3];
    const int*   csrc = (const int*)d_in[6];
    const int*   cdst = (const int*)d_in[7];

    const float* W_ac_q = (const float*)d_in[10]; const float* b_ac_q = (const float*)d_in[11];
    const float* W_ac_t = (const float*)d_in[12]; const float* b_ac_t = (const float*)d_in[13];
    const float* W_vc_q = (const float*)d_in[14]; const float* b_vc_q = (const float*)d_in[15];
    const float* W_vc_t = (const float*)d_in[16]; const float* b_vc_t = (const float*)d_in[17];
    const float* W_mq   = (const float*)d_in[18]; const float* b_mq   = (const float*)d_in[19];
    const float* W_mt   = (const float*)d_in[20]; const float* b_mt   = (const float*)d_in[21];
    const float* W_aq   = (const float*)d_in[22]; const float* b_aq   = (const float*)d_in[23];
    const float* W_vq   = (const float*)d_in[24]; const float* b_vq   = (const float*)d_in[25];
    const float* W_at   = (const float*)d_in[26]; const float* b_at   = (const float*)d_in[27];
    const float* W_vt   = (const float*)d_in[28]; const float* b_vt   = (const float*)d_in[29];

    float* outQ = (float*)d_out;
    float* outT = outQ + SZ;

    cudaMemsetAsync(S + O_MV,   0, (O_ZEND - O_MV) * sizeof(float), 0);
    cudaMemsetAsync(S + O_XQ2T, 0, SZ * sizeof(float), 0);
    cudaMemsetAsync(S + O_QSUM, 0, kD * sizeof(float), 0);

    // ---- stage 1: 4 ELU node transforms, one launch (512 CTAs) ----
    {
        GemmBatch b;
        b.j[0] = {Xq, nullptr, 128, 128, W_ac_q, b_ac_q, S + O_XQ_AC, 1};
        b.j[1] = {Xt, nullptr, 128, 128, W_ac_t, b_ac_t, S + O_XT_AC, 1};
        b.j[2] = {Xq, nullptr, 128, 128, W_vc_q, b_vc_q, S + O_XQ_VC, 1};
        b.j[3] = {Xt, nullptr, 128, 128, W_vc_t, b_vc_t, S + O_XT_VC, 1};
        sgemm_n128_b<<<dim3(128, 4), 256>>>(b);
    }

    colsum_kernel<<<kNQ / 128, 128>>>(Xq, S + O_QSUM);
    bias_mt_kernel<<<1, 128>>>(S + O_QSUM, W_mt, b_mt, S + O_BIAS);

    // ---- cross attention ----
    cross_logits_kernel<<<(kEC * 32) / 256, 256>>>(csrc, cdst, S + O_XQ_AC, S + O_XT_AC,
                                                   S + O_LC, (unsigned*)(S + O_MV), (int*)(S + O_CNT));
    {
        ExpBatch b;
        b.j[0] = {S + O_LC, cdst, (unsigned*)(S + O_MV), S + O_SV};
        b.j[1] = b.j[0];
        seg_expsum_b<<<dim3(kEC / 256, 1), 256>>>(b, kEC);
    }
    fill_t2q_kernel<<<SZ / 256, 256>>>((int*)(S + O_CNT), S + O_XT_VC, S + O_XT2Q);
    {
        ScatBatch b;
        b.j[0] = {S + O_LC, csrc, cdst, (unsigned*)(S + O_MV), S + O_SV, S + O_XQ_VC, S + O_XQ2T};
        b.j[1] = b.j[0];
        seg_scatter_b<<<dim3((kEC * 32) / 256, 1), 256>>>(b, kEC);
    }

    // ---- stage 2: merged features (K=256), one launch (256 CTAs) ----
    {
        GemmBatch b;
        b.j[0] = {Xq, S + O_XT2Q, 128, 256, W_mq, b_mq,      S + O_XQM, 0};
        b.j[1] = {Xt, S + O_XQ2T, 128, 256, W_mt, S + O_BIAS, S + O_XTM, 0};
        b.j[2] = b.j[0]; b.j[3] = b.j[0];
        sgemm_n128_b<<<dim3(128, 2), 256>>>(b);
    }

    // ---- stage 3: 4 intra projections, one launch (512 CTAs) ----
    {
        GemmBatch b;
        b.j[0] = {S + O_XTM, nullptr, 128, 128, W_vt,            nullptr, S + O_PS_T, 0};
        b.j[1] = {S + O_XTM, nullptr, 128, 128, W_vt + 128 * kD, b_vt,    S + O_PD_T, 0};
        b.j[2] = {S + O_XQM, nullptr, 128, 128, W_vq,            nullptr, S + O_PS_Q, 0};
        b.j[3] = {S + O_XQM, nullptr, 128, 128, W_vq + 128 * kD, b_vq,    S + O_PD_Q, 0};
        sgemm_n128_b<<<dim3(128, 4), 256>>>(b);
    }

    {
        NsBatch b;
        b.j[0] = {S + O_XTM, W_at, b_at, S + O_SSRC_T, S + O_SDST_T};
        b.j[1] = {S + O_XQM, W_aq, b_aq, S + O_SSRC_Q, S + O_SDST_Q};
        node_scalars_b<<<dim3((kNT * 32) / 256, 2), 256>>>(b, kNT);
    }
    {
        IlBatch b;
        b.j[0] = {et, et + kET, S + O_SSRC_T, S + O_SDST_T, S + O_LT, (unsigned*)(S + O_MT)};
        b.j[1] = {eq, eq + kEQ, S + O_SSRC_Q, S + O_SDST_Q, S + O_LQ, (unsigned*)(S + O_MQ)};
        intra_logits_b<<<dim3(kET / 256, 2), 256>>>(b, kET);
    }
    {
        ExpBatch b;
        b.j[0] = {S + O_LT, et + kET, (unsigned*)(S + O_MT), S + O_ST};
        b.j[1] = {S + O_LQ, eq + kEQ, (unsigned*)(S + O_MQ), S + O_SQ};
        seg_expsum_b<<<dim3(kET / 256, 2), 256>>>(b, kET);
    }
    {
        IoBatch b;
        b.j[0] = {S + O_ST, S + O_PD_T, outT};
        b.j[1] = {S + O_SQ, S + O_PD_Q, outQ};
        init_out_b<<<dim3(SZ / 256, 2), 256>>>(b);
    }
    {
        ScatBatch b;
        b.j[0] = {S + O_LT, et, et + kET, (unsigned*)(S + O_MT), S + O_ST, S + O_PS_T, outT};
        b.j[1] = {S + O_LQ, eq, eq + kEQ, (unsigned*)(S + O_MQ), S + O_SQ, S + O_PS_Q, outQ};
        seg_scatter_b<<<dim3((kET * 32) / 256, 2), 256>>>(b, kET);
    }
}

// round 4
// speedup vs baseline: 1.3129x; 1.1276x over previous
#include <cuda_runtime.h>
#include <math.h>

// Problem constants
constexpr int kNQ = 8192;
constexpr int kNT = 8192;
constexpr int kD  = 128;
constexpr int kEC = 262144;
constexpr int kEQ = 262144;
constexpr int kET = 262144;

constexpr size_t SZ = (size_t)kNQ * kD;

// ---- scratch layout (floats) ----
constexpr size_t O_XQ_AC = 0;
constexpr size_t O_XT_AC = 1*SZ;
constexpr size_t O_XQ_VC = 2*SZ;
constexpr size_t O_XT_VC = 3*SZ;
constexpr size_t O_XT2Q  = 4*SZ;
constexpr size_t O_XQ2T  = 5*SZ;
constexpr size_t O_XQM   = 6*SZ;
constexpr size_t O_XTM   = 7*SZ;
constexpr size_t O_PS_T  = 8*SZ;
constexpr size_t O_PD_T  = 9*SZ;
constexpr size_t O_PS_Q  = 10*SZ;
constexpr size_t O_PD_Q  = 11*SZ;
constexpr size_t O_LC    = 12*SZ;
constexpr size_t O_LT    = O_LC + kEC;
constexpr size_t O_LQ    = O_LT + kET;
constexpr size_t O_MV    = O_LQ + kEQ;   // zero-init block start
constexpr size_t O_SV    = O_MV + kNT;
constexpr size_t O_CNT   = O_SV + kNT;
constexpr size_t O_MT    = O_CNT + kNQ;
constexpr size_t O_ST    = O_MT + kNT;
constexpr size_t O_MQ    = O_ST + kNT;
constexpr size_t O_SQ    = O_MQ + kNQ;
constexpr size_t O_ZEND  = O_SQ + kNQ;
constexpr size_t O_SSRC_T= O_ZEND;
constexpr size_t O_SDST_T= O_SSRC_T + kNT;
constexpr size_t O_SSRC_Q= O_SDST_T + kNT;
constexpr size_t O_SDST_Q= O_SSRC_Q + kNQ;
constexpr size_t O_QSUM  = O_SDST_Q + kNQ;
constexpr size_t O_BIAS  = O_QSUM + kD;
constexpr size_t O_TOTAL = O_BIAS + kD;

__device__ __align__(16) float g_scratch[O_TOTAL];

__device__ __forceinline__ unsigned fkey(float f) {
    unsigned u = __float_as_uint(f);
    return (u & 0x80000000u) ? ~u : (u | 0x80000000u);
}
__device__ __forceinline__ float funkey(unsigned u) {
    return (u & 0x80000000u) ? __uint_as_float(u & 0x7fffffffu)
                             : __uint_as_float(~u);
}

// ============================================================
// Batched tiled SGEMM (unchanged from R2).
// ============================================================
struct GemmJob {
    const float* A0; const float* A1;
    int K0; int K;
    const float* W; const float* bias;
    float* C; int act;
};
struct GemmBatch { GemmJob j[4]; };

__global__ void sgemm_n128_b(const __grid_constant__ GemmBatch batch)
{
    const GemmJob& J = batch.j[blockIdx.y];

    __shared__ float As[32][65];
    __shared__ float Bs[32][128];
    const int tid = threadIdx.x;
    const int tx = tid & 31;
    const int ty = tid >> 5;
    const int m0 = blockIdx.x * 64;

    float acc[8][4];
    #pragma unroll
    for (int i = 0; i < 8; i++)
        #pragma unroll
        for (int j = 0; j < 4; j++) acc[i][j] = 0.f;

    const int K = J.K, K0 = J.K0;
    for (int kt = 0; kt < K; kt += 32) {
        const float* Ap; int ldA, kb;
        if (kt < K0) { Ap = J.A0; ldA = K0;     kb = kt; }
        else         { Ap = J.A1; ldA = K - K0; kb = kt - K0; }

        #pragma unroll
        for (int i = 0; i < 2; i++) {
            int t   = tid + i * 256;
            int row = t >> 3;
            int c4  = t & 7;
            float4 v = *reinterpret_cast<const float4*>(Ap + (size_t)(m0 + row) * ldA + kb + c4 * 4);
            As[c4*4+0][row] = v.x;
            As[c4*4+1][row] = v.y;
            As[c4*4+2][row] = v.z;
            As[c4*4+3][row] = v.w;
        }
        #pragma unroll
        for (int i = 0; i < 4; i++) {
            int t  = tid + i * 256;
            int r  = t >> 5;
            int c4 = t & 31;
            float4 v = *reinterpret_cast<const float4*>(J.W + (size_t)(kt + r) * 128 + c4 * 4);
            *reinterpret_cast<float4*>(&Bs[r][c4 * 4]) = v;
        }
        __syncthreads();

        #pragma unroll
        for (int k = 0; k < 32; k++) {
            float a[8], b[4];
            #pragma unroll
            for (int i = 0; i < 8; i++) a[i] = As[k][ty * 8 + i];
            #pragma unroll
            for (int j = 0; j < 4; j++) b[j] = Bs[k][tx * 4 + j];
            #pragma unroll
            for (int i = 0; i < 8; i++)
                #pragma unroll
                for (int j = 0; j < 4; j++)
                    acc[i][j] = fmaf(a[i], b[j], acc[i][j]);
        }
        __syncthreads();
    }

    float bj[4] = {0.f, 0.f, 0.f, 0.f};
    if (J.bias) {
        #pragma unroll
        for (int j = 0; j < 4; j++) bj[j] = J.bias[tx * 4 + j];
    }
    const int act = J.act;
    #pragma unroll
    for (int i = 0; i < 8; i++) {
        int row = m0 + ty * 8 + i;
        float v0 = acc[i][0] + bj[0];
        float v1 = acc[i][1] + bj[1];
        float v2 = acc[i][2] + bj[2];
        float v3 = acc[i][3] + bj[3];
        if (act) {
            v0 = v0 > 0.f ? v0 : expm1f(v0);
            v1 = v1 > 0.f ? v1 : expm1f(v1);
            v2 = v2 > 0.f ? v2 : expm1f(v2);
            v3 = v3 > 0.f ? v3 : expm1f(v3);
        }
        float4 o = {v0, v1, v2, v3};
        *reinterpret_cast<float4*>(J.C + (size_t)row * 128 + tx * 4) = o;
    }
}

__global__ void colsum_kernel(const float* __restrict__ X, float* __restrict__ sums)
{
    int j  = threadIdx.x;
    int r0 = blockIdx.x * 128;
    float s = 0.f;
    for (int r = 0; r < 128; r++) s += X[(size_t)(r0 + r) * kD + j];
    atomicAdd(&sums[j], s);
}

__global__ void bias_mt_kernel(const float* __restrict__ qsum, const float* __restrict__ W_mt,
                               const float* __restrict__ b_mt, float* __restrict__ be)
{
    int j = threadIdx.x;
    float s = b_mt[j];
    const float inv = 1.0f / (float)kNQ;
    for (int k = 0; k < kD; k++)
        s = fmaf(qsum[k] * inv, W_mt[(size_t)(256 + k) * kD + j], s);
    be[j] = s;
}

// ============================================================
// cross logits: 4 edges per warp, all 8 row-gathers batched up front
// ============================================================
__global__ void cross_logits_kernel(const int* __restrict__ src, const int* __restrict__ dst,
                                    const float* __restrict__ Aq, const float* __restrict__ At,
                                    float* __restrict__ logits, unsigned* __restrict__ m_v,
                                    int* __restrict__ cnt_u)
{
    int gtid = blockIdx.x * blockDim.x + threadIdx.x;
    int warp = gtid >> 5;
    int lane = gtid & 31;
    int e0 = warp * 4;

    // lanes 0..3 hold src[e0+lane], lanes 4..7 hold dst[e0+lane-4]
    int idxv = 0;
    if (lane < 8) {
        int e = e0 + (lane & 3);
        idxv = (lane < 4) ? src[e] : dst[e];
    }
    int vv = __shfl_sync(0xffffffffu, idxv, 4 + (lane & 3));  // dst for "my" edge (lanes 0-3)

    // gather all 8 feature rows first -> MLP = 8 per warp
    float4 a[4], b[4];
    #pragma unroll
    for (int k = 0; k < 4; k++) {
        int u = __shfl_sync(0xffffffffu, idxv, k);
        int v = __shfl_sync(0xffffffffu, idxv, 4 + k);
        a[k] = *reinterpret_cast<const float4*>(Aq + (size_t)u * kD + lane * 4);
        b[k] = *reinterpret_cast<const float4*>(At + (size_t)v * kD + lane * 4);
    }
    float p[4];
    #pragma unroll
    for (int k = 0; k < 4; k++)
        p[k] = a[k].x * b[k].x + a[k].y * b[k].y + a[k].z * b[k].z + a[k].w * b[k].w;

    #pragma unroll
    for (int o = 16; o; o >>= 1) {
        #pragma unroll
        for (int k = 0; k < 4; k++) p[k] += __shfl_xor_sync(0xffffffffu, p[k], o);
    }

    if (lane < 4) {
        float pl = p[0];
        if (lane == 1) pl = p[1];
        if (lane == 2) pl = p[2];
        if (lane == 3) pl = p[3];
        logits[e0 + lane] = pl;
        atomicMax(&m_v[vv], fkey(pl));
        atomicAdd(&cnt_u[idxv], 1);
    }
}

// ============================================================
// batched s[seg] += exp(l - m[seg]) — 2 edges per thread (int2/float2)
// ============================================================
struct ExpJob { const float* logits; const int* seg; const unsigned* m; float* s; };
struct ExpBatch { ExpJob j[2]; };
__global__ void seg_expsum_b(const __grid_constant__ ExpBatch batch, int E)
{
    const ExpJob& J = batch.j[blockIdx.y];
    int e = (blockIdx.x * blockDim.x + threadIdx.x) * 2;
    if (e >= E) return;
    int2   d2 = *reinterpret_cast<const int2*>(J.seg + e);
    float2 l2 = *reinterpret_cast<const float2*>(J.logits + e);
    unsigned m0 = J.m[d2.x];
    unsigned m1 = J.m[d2.y];
    atomicAdd(&J.s[d2.x], expf(l2.x - funkey(m0)));
    atomicAdd(&J.s[d2.y], expf(l2.y - funkey(m1)));
}

__global__ void fill_t2q_kernel(const int* __restrict__ cnt, const float* __restrict__ V,
                                float* __restrict__ out)
{
    size_t i = (size_t)blockIdx.x * blockDim.x + threadIdx.x;
    int n = (int)(i >> 7);
    out[i] = (cnt[n] > 0) ? V[i] : 0.f;
}

// ============================================================
// batched softmax scatter: 4 edges per warp, V-row gathers batched up front
// ============================================================
struct ScatJob {
    const float* logits; const int* gat; const int* seg;
    const unsigned* m; const float* s; const float* V; float* out;
};
struct ScatBatch { ScatJob j[2]; };
__global__ void seg_scatter_b(const __grid_constant__ ScatBatch batch, int E)
{
    const ScatJob& J = batch.j[blockIdx.y];
    int gtid = blockIdx.x * blockDim.x + threadIdx.x;
    int warp = gtid >> 5;
    int lane = gtid & 31;
    int e0 = warp * 4;

    // lanes 0..3 compute per-edge scalars
    float a_l = 0.f; int g_l = 0, d_l = 0;
    if (lane < 4) {
        int e = e0 + lane;
        g_l = J.gat[e];
        d_l = J.seg[e];
        a_l = expf(J.logits[e] - funkey(J.m[d_l])) / J.s[d_l];
    }

    float4 v[4]; float aa[4]; int dd[4];
    #pragma unroll
    for (int k = 0; k < 4; k++) {
        int g  = __shfl_sync(0xffffffffu, g_l, k);
        dd[k]  = __shfl_sync(0xffffffffu, d_l, k);
        aa[k]  = __shfl_sync(0xffffffffu, a_l, k);
        v[k]   = *reinterpret_cast<const float4*>(J.V + (size_t)g * kD + lane * 4);
    }
    #pragma unroll
    for (int k = 0; k < 4; k++) {
        float* p = J.out + (size_t)dd[k] * kD + lane * 4;
        asm volatile("red.global.add.v4.f32 [%0], {%1,%2,%3,%4};"
                     :: "l"(p), "f"(aa[k] * v[k].x), "f"(aa[k] * v[k].y),
                        "f"(aa[k] * v[k].z), "f"(aa[k] * v[k].w)
                     : "memory");
    }
}

// batched per-node attention scalars
struct NsJob { const float* H; const float* Wa; const float* ba; float* ssrc; float* sdst; };
struct NsBatch { NsJob j[2]; };
__global__ void node_scalars_b(const __grid_constant__ NsBatch batch, int N)
{
    const NsJob& J = batch.j[blockIdx.y];
    int idx  = blockIdx.x * blockDim.x + threadIdx.x;
    int n    = idx >> 5;
    int lane = idx & 31;
    if (n >= N) return;
    float4 h  = *reinterpret_cast<const float4*>(J.H  + (size_t)n * kD + lane * 4);
    float4 w0 = *reinterpret_cast<const float4*>(J.Wa + lane * 4);
    float4 w1 = *reinterpret_cast<const float4*>(J.Wa + 128 + lane * 4);
    float p0 = h.x * w0.x + h.y * w0.y + h.z * w0.z + h.w * w0.w;
    float p1 = h.x * w1.x + h.y * w1.y + h.z * w1.z + h.w * w1.w;
    #pragma unroll
    for (int o = 16; o; o >>= 1) {
        p0 += __shfl_xor_sync(0xffffffffu, p0, o);
        p1 += __shfl_xor_sync(0xffffffffu, p1, o);
    }
    if (lane == 0) { J.ssrc[n] = p0; J.sdst[n] = p1 + J.ba[0]; }
}

// batched intra edge logits — 2 edges per thread
struct IlJob { const int* src; const int* dst; const float* ssrc; const float* sdst;
               float* logits; unsigned* m; };
struct IlBatch { IlJob j[2]; };
__global__ void intra_logits_b(const __grid_constant__ IlBatch batch, int E)
{
    const IlJob& J = batch.j[blockIdx.y];
    int e = (blockIdx.x * blockDim.x + threadIdx.x) * 2;
    if (e >= E) return;
    int2 s2 = *reinterpret_cast<const int2*>(J.src + e);
    int2 d2 = *reinterpret_cast<const int2*>(J.dst + e);
    float l0 = J.ssrc[s2.x] + J.sdst[d2.x];
    float l1 = J.ssrc[s2.y] + J.sdst[d2.y];
    float2 l = {l0, l1};
    *reinterpret_cast<float2*>(J.logits + e) = l;
    atomicMax(&J.m[d2.x], fkey(l0));
    atomicMax(&J.m[d2.y], fkey(l1));
}

// batched: out[n,:] = (s[n] > 0) ? Pdst[n,:] : 0
struct IoJob { const float* s; const float* pd; float* out; };
struct IoBatch { IoJob j[2]; };
__global__ void init_out_b(const __grid_constant__ IoBatch batch)
{
    const IoJob& J = batch.j[blockIdx.y];
    size_t i = (size_t)blockIdx.x * blockDim.x + threadIdx.x;
    int n = (int)(i >> 7);
    J.out[i] = (J.s[n] > 0.f) ? J.pd[i] : 0.f;
}

// ============================================================
extern "C" void kernel_launch(void* const* d_in, const int* in_sizes, int n_in,
                              void* d_out, int out_size)
{
    (void)in_sizes; (void)n_in; (void)out_size;
    float* S = nullptr;
    cudaGetSymbolAddress((void**)&S, g_scratch);

    const float* Xq   = (const float*)d_in[0];
    const int*   eq   = (const int*)d_in[1];
    const float* Xt   = (const float*)d_in[2];
    const int*   et   = (const int*)d_in[3];
    const int*   csrc = (const int*)d_in[6];
    const int*   cdst = (const int*)d_in[7];

    const float* W_ac_q = (const float*)d_in[10]; const float* b_ac_q = (const float*)d_in[11];
    const float* W_ac_t = (const float*)d_in[12]; const float* b_ac_t = (const float*)d_in[13];
    const float* W_vc_q = (const float*)d_in[14]; const float* b_vc_q = (const float*)d_in[15];
    const float* W_vc_t = (const float*)d_in[16]; const float* b_vc_t = (const float*)d_in[17];
    const float* W_mq   = (const float*)d_in[18]; const float* b_mq   = (const float*)d_in[19];
    const float* W_mt   = (const float*)d_in[20]; const float* b_mt   = (const float*)d_in[21];
    const float* W_aq   = (const float*)d_in[22]; const float* b_aq   = (const float*)d_in[23];
    const float* W_vq   = (const float*)d_in[24]; const float* b_vq   = (const float*)d_in[25];
    const float* W_at   = (const float*)d_in[26]; const float* b_at   = (const float*)d_in[27];
    const float* W_vt   = (const float*)d_in[28]; const float* b_vt   = (const float*)d_in[29];

    float* outQ = (float*)d_out;
    float* outT = outQ + SZ;

    cudaMemsetAsync(S + O_MV,   0, (O_ZEND - O_MV) * sizeof(float), 0);
    cudaMemsetAsync(S + O_XQ2T, 0, SZ * sizeof(float), 0);
    cudaMemsetAsync(S + O_QSUM, 0, kD * sizeof(float), 0);

    // ---- stage 1: 4 ELU node transforms ----
    {
        GemmBatch b;
        b.j[0] = {Xq, nullptr, 128, 128, W_ac_q, b_ac_q, S + O_XQ_AC, 1};
        b.j[1] = {Xt, nullptr, 128, 128, W_ac_t, b_ac_t, S + O_XT_AC, 1};
        b.j[2] = {Xq, nullptr, 128, 128, W_vc_q, b_vc_q, S + O_XQ_VC, 1};
        b.j[3] = {Xt, nullptr, 128, 128, W_vc_t, b_vc_t, S + O_XT_VC, 1};
        sgemm_n128_b<<<dim3(128, 4), 256>>>(b);
    }

    colsum_kernel<<<kNQ / 128, 128>>>(Xq, S + O_QSUM);
    bias_mt_kernel<<<1, 128>>>(S + O_QSUM, W_mt, b_mt, S + O_BIAS);

    // ---- cross attention ----
    // 4 edges/warp -> kEC/4 warps -> (kEC/4*32)/256 blocks
    cross_logits_kernel<<<(kEC / 4) * 32 / 256, 256>>>(csrc, cdst, S + O_XQ_AC, S + O_XT_AC,
                                                       S + O_LC, (unsigned*)(S + O_MV), (int*)(S + O_CNT));
    {
        ExpBatch b;
        b.j[0] = {S + O_LC, cdst, (unsigned*)(S + O_MV), S + O_SV};
        b.j[1] = b.j[0];
        seg_expsum_b<<<dim3(kEC / 512, 1), 256>>>(b, kEC);
    }
    fill_t2q_kernel<<<SZ / 256, 256>>>((int*)(S + O_CNT), S + O_XT_VC, S + O_XT2Q);
    {
        ScatBatch b;
        b.j[0] = {S + O_LC, csrc, cdst, (unsigned*)(S + O_MV), S + O_SV, S + O_XQ_VC, S + O_XQ2T};
        b.j[1] = b.j[0];
        seg_scatter_b<<<dim3((kEC / 4) * 32 / 256, 1), 256>>>(b, kEC);
    }

    // ---- stage 2: merged features (K=256) ----
    {
        GemmBatch b;
        b.j[0] = {Xq, S + O_XT2Q, 128, 256, W_mq, b_mq,       S + O_XQM, 0};
        b.j[1] = {Xt, S + O_XQ2T, 128, 256, W_mt, S + O_BIAS, S + O_XTM, 0};
        b.j[2] = b.j[0]; b.j[3] = b.j[0];
        sgemm_n128_b<<<dim3(128, 2), 256>>>(b);
    }

    // ---- stage 3: 4 intra projections ----
    {
        GemmBatch b;
        b.j[0] = {S + O_XTM, nullptr, 128, 128, W_vt,            nullptr, S + O_PS_T, 0};
        b.j[1] = {S + O_XTM, nullptr, 128, 128, W_vt + 128 * kD, b_vt,    S + O_PD_T, 0};
        b.j[2] = {S + O_XQM, nullptr, 128, 128, W_vq,            nullptr, S + O_PS_Q, 0};
        b.j[3] = {S + O_XQM, nullptr, 128, 128, W_vq + 128 * kD, b_vq,    S + O_PD_Q, 0};
        sgemm_n128_b<<<dim3(128, 4), 256>>>(b);
    }

    {
        NsBatch b;
        b.j[0] = {S + O_XTM, W_at, b_at, S + O_SSRC_T, S + O_SDST_T};
        b.j[1] = {S + O_XQM, W_aq, b_aq, S + O_SSRC_Q, S + O_SDST_Q};
        node_scalars_b<<<dim3((kNT * 32) / 256, 2), 256>>>(b, kNT);
    }
    {
        IlBatch b;
        b.j[0] = {et, et + kET, S + O_SSRC_T, S + O_SDST_T, S + O_LT, (unsigned*)(S + O_MT)};
        b.j[1] = {eq, eq + kEQ, S + O_SSRC_Q, S + O_SDST_Q, S + O_LQ, (unsigned*)(S + O_MQ)};
        intra_logits_b<<<dim3(kET / 512, 2), 256>>>(b, kET);
    }
    {
        ExpBatch b;
        b.j[0] = {S + O_LT, et + kET, (unsigned*)(S + O_MT), S + O_ST};
        b.j[1] = {S + O_LQ, eq + kEQ, (unsigned*)(S + O_MQ), S + O_SQ};
        seg_expsum_b<<<dim3(kET / 512, 2), 256>>>(b, kET);
    }
    {
        IoBatch b;
        b.j[0] = {S + O_ST, S + O_PD_T, outT};
        b.j[1] = {S + O_SQ, S + O_PD_Q, outQ};
        init_out_b<<<dim3(SZ / 256, 2), 256>>>(b);
    }
    {
        ScatBatch b;
        b.j[0] = {S + O_LT, et, et + kET, (unsigned*)(S + O_MT), S + O_ST, S + O_PS_T, outT};
        b.j[1] = {S + O_LQ, eq, eq + kEQ, (unsigned*)(S + O_MQ), S + O_SQ, S + O_PS_Q, outQ};
        seg_scatter_b<<<dim3((kET / 4) * 32 / 256, 2), 256>>>(b, kET);
    }
}

// round 5
// speedup vs baseline: 1.4918x; 1.1363x over previous
#include <cuda_runtime.h>
#include <math.h>

// Problem constants
constexpr int kNQ = 8192;
constexpr int kNT = 8192;
constexpr int kD  = 128;
constexpr int kEC = 262144;
constexpr int kEQ = 262144;
constexpr int kET = 262144;

constexpr size_t SZ = (size_t)kNQ * kD;

// ---- scratch layout (floats) ----
constexpr size_t O_XQ_AC = 0;
constexpr size_t O_XT_AC = 1*SZ;
constexpr size_t O_XQ_VC = 2*SZ;
constexpr size_t O_XT_VC = 3*SZ;
constexpr size_t O_ACC   = 4*SZ;      // unnormalized Xq2t accumulator
constexpr size_t O_XQM   = 5*SZ;
constexpr size_t O_XTM   = 6*SZ;
constexpr size_t O_PS_T  = 7*SZ;
constexpr size_t O_PD_T  = 8*SZ;
constexpr size_t O_PS_Q  = 9*SZ;
constexpr size_t O_PD_Q  = 10*SZ;
// zero-init scalar block
constexpr size_t O_SV    = 11*SZ;          // cross softmax denom (per t-node)
constexpr size_t O_CNT   = O_SV + kNT;     // cross edge count per q-node (as float)
constexpr size_t O_ST    = O_CNT + kNQ;    // intra-T softmax denom
constexpr size_t O_SQ    = O_ST + kNT;     // intra-Q softmax denom
constexpr size_t O_QSUM  = O_SQ + kNQ;
constexpr size_t O_ZEND  = O_QSUM + kD;
// non-zeroed scalars
constexpr size_t O_SSRC_T= O_ZEND;
constexpr size_t O_SDST_T= O_SSRC_T + kNT;
constexpr size_t O_SSRC_Q= O_SDST_T + kNT;
constexpr size_t O_SDST_Q= O_SSRC_Q + kNQ;
constexpr size_t O_BIAS  = O_SDST_Q + kNQ;
constexpr size_t O_TOTAL = O_BIAS + kD;

__device__ __align__(16) float g_scratch[O_TOTAL];

// ============================================================
// Batched tiled SGEMM, templated on BM.
// C[M,128] = act( [A0|A1][M,K] @ W[K,128] + bias )
// A1 rows optionally scaled at load: smode 1 -> *(1/s1[r]) (0 if s<=0),
// smode 2 -> mask (s1[r] > 0). 256 threads, thread tile (BM/8) x 4.
// ============================================================
struct GemmJob {
    const float* A0; const float* A1;
    int K0; int K;
    const float* W; const float* bias;
    float* C; int act;
    const float* s1; int smode;
};
struct GemmBatch { GemmJob j[4]; };

template<int BM>
__global__ void sgemm_b(const __grid_constant__ GemmBatch batch)
{
    constexpr int TM = BM / 8;
    const GemmJob& J = batch.j[blockIdx.y];

    __shared__ float As[32][BM + 1];
    __shared__ float Bs[32][128];
    const int tid = threadIdx.x;
    const int tx = tid & 31;
    const int ty = tid >> 5;
    const int m0 = blockIdx.x * BM;

    float acc[TM][4];
    #pragma unroll
    for (int i = 0; i < TM; i++)
        #pragma unroll
        for (int j = 0; j < 4; j++) acc[i][j] = 0.f;

    const int K = J.K, K0 = J.K0;
    for (int kt = 0; kt < K; kt += 32) {
        const bool inA1 = (kt >= K0);
        const float* Ap = inA1 ? J.A1 : J.A0;
        const int ldA   = inA1 ? (K - K0) : K0;
        const int kb    = inA1 ? (kt - K0) : kt;

        #pragma unroll
        for (int i = 0; i < BM / 32; i++) {
            int t   = tid + i * 256;
            int row = t >> 3;
            int c4  = t & 7;
            float4 v = *reinterpret_cast<const float4*>(Ap + (size_t)(m0 + row) * ldA + kb + c4 * 4);
            if (inA1 && J.smode) {
                float sv = J.s1[m0 + row];
                float f = (J.smode == 1) ? (sv > 0.f ? 1.f / sv : 0.f)
                                         : (sv > 0.f ? 1.f : 0.f);
                v.x *= f; v.y *= f; v.z *= f; v.w *= f;
            }
            As[c4*4+0][row] = v.x;
            As[c4*4+1][row] = v.y;
            As[c4*4+2][row] = v.z;
            As[c4*4+3][row] = v.w;
        }
        #pragma unroll
        for (int i = 0; i < 4; i++) {
            int t  = tid + i * 256;
            int r  = t >> 5;
            int c4 = t & 31;
            float4 v = *reinterpret_cast<const float4*>(J.W + (size_t)(kt + r) * 128 + c4 * 4);
            *reinterpret_cast<float4*>(&Bs[r][c4 * 4]) = v;
        }
        __syncthreads();

        #pragma unroll
        for (int k = 0; k < 32; k++) {
            float a[TM], b[4];
            #pragma unroll
            for (int i = 0; i < TM; i++) a[i] = As[k][ty * TM + i];
            #pragma unroll
            for (int j = 0; j < 4; j++) b[j] = Bs[k][tx * 4 + j];
            #pragma unroll
            for (int i = 0; i < TM; i++)
                #pragma unroll
                for (int j = 0; j < 4; j++)
                    acc[i][j] = fmaf(a[i], b[j], acc[i][j]);
        }
        __syncthreads();
    }

    float bj[4] = {0.f, 0.f, 0.f, 0.f};
    if (J.bias) {
        #pragma unroll
        for (int j = 0; j < 4; j++) bj[j] = J.bias[tx * 4 + j];
    }
    const int act = J.act;
    #pragma unroll
    for (int i = 0; i < TM; i++) {
        int row = m0 + ty * TM + i;
        float v0 = acc[i][0] + bj[0];
        float v1 = acc[i][1] + bj[1];
        float v2 = acc[i][2] + bj[2];
        float v3 = acc[i][3] + bj[3];
        if (act) {
            v0 = v0 > 0.f ? v0 : expm1f(v0);
            v1 = v1 > 0.f ? v1 : expm1f(v1);
            v2 = v2 > 0.f ? v2 : expm1f(v2);
            v3 = v3 > 0.f ? v3 : expm1f(v3);
        }
        float4 o = {v0, v1, v2, v3};
        *reinterpret_cast<float4*>(J.C + (size_t)row * 128 + tx * 4) = o;
    }
}

__global__ void colsum_kernel(const float* __restrict__ X, float* __restrict__ sums)
{
    int j  = threadIdx.x;
    int r0 = blockIdx.x * 128;
    float s = 0.f;
    for (int r = 0; r < 128; r++) s += X[(size_t)(r0 + r) * kD + j];
    atomicAdd(&sums[j], s);
}

__global__ void bias_mt_kernel(const float* __restrict__ qsum, const float* __restrict__ W_mt,
                               const float* __restrict__ b_mt, float* __restrict__ be)
{
    int j = threadIdx.x;
    float s = b_mt[j];
    const float inv = 1.0f / (float)kNQ;
    for (int k = 0; k < kD; k++)
        s = fmaf(qsum[k] * inv, W_mt[(size_t)(256 + k) * kD + j], s);
    be[j] = s;
}

// ============================================================
// Fused cross attention: per 4 edges (one warp):
//   p = dot(Aq[src], At[dst]);  w = exp(p)   (no max shift — range-safe)
//   s_v[dst] += w;  cnt[src] += 1;  acc[dst,:] += w * Vq[src,:]
// ============================================================
__global__ void cross_fused(const int* __restrict__ src, const int* __restrict__ dst,
                            const float* __restrict__ Aq, const float* __restrict__ At,
                            const float* __restrict__ Vq,
                            float* __restrict__ s_v, float* __restrict__ cnt_u,
                            float* __restrict__ acc)
{
    int gtid = blockIdx.x * blockDim.x + threadIdx.x;
    int warp = gtid >> 5;
    int lane = gtid & 31;
    int e0 = warp * 4;

    int idxv = 0;
    if (lane < 8) {
        int e = e0 + (lane & 3);
        idxv = (lane < 4) ? src[e] : dst[e];
    }
    int uu[4], dd[4];
    #pragma unroll
    for (int k = 0; k < 4; k++) {
        uu[k] = __shfl_sync(0xffffffffu, idxv, k);
        dd[k] = __shfl_sync(0xffffffffu, idxv, 4 + k);
    }

    // 12 independent row gathers batched up front
    float4 a[4], b[4], vv[4];
    #pragma unroll
    for (int k = 0; k < 4; k++) {
        a[k]  = *reinterpret_cast<const float4*>(Aq + (size_t)uu[k] * kD + lane * 4);
        b[k]  = *reinterpret_cast<const float4*>(At + (size_t)dd[k] * kD + lane * 4);
        vv[k] = *reinterpret_cast<const float4*>(Vq + (size_t)uu[k] * kD + lane * 4);
    }

    float w[4];
    #pragma unroll
    for (int k = 0; k < 4; k++)
        w[k] = a[k].x * b[k].x + a[k].y * b[k].y + a[k].z * b[k].z + a[k].w * b[k].w;
    #pragma unroll
    for (int o = 16; o; o >>= 1) {
        #pragma unroll
        for (int k = 0; k < 4; k++) w[k] += __shfl_xor_sync(0xffffffffu, w[k], o);
    }
    #pragma unroll
    for (int k = 0; k < 4; k++) w[k] = expf(w[k]);

    // lanes 0-3 update the scalar accumulators for their own edge
    {
        float wl = w[0]; int dl = dd[0], ul = uu[0];
        if (lane == 1) { wl = w[1]; dl = dd[1]; ul = uu[1]; }
        if (lane == 2) { wl = w[2]; dl = dd[2]; ul = uu[2]; }
        if (lane == 3) { wl = w[3]; dl = dd[3]; ul = uu[3]; }
        if (lane < 4) {
            atomicAdd(&s_v[dl], wl);
            atomicAdd(&cnt_u[ul], 1.0f);
        }
    }

    #pragma unroll
    for (int k = 0; k < 4; k++) {
        float* p = acc + (size_t)dd[k] * kD + lane * 4;
        asm volatile("red.global.add.v4.f32 [%0], {%1,%2,%3,%4};"
                     :: "l"(p), "f"(w[k] * vv[k].x), "f"(w[k] * vv[k].y),
                        "f"(w[k] * vv[k].z), "f"(w[k] * vv[k].w)
                     : "memory");
    }
}

// batched per-node attention scalars
struct NsJob { const float* H; const float* Wa; const float* ba; float* ssrc; float* sdst; };
struct NsBatch { NsJob j[2]; };
__global__ void node_scalars_b(const __grid_constant__ NsBatch batch, int N)
{
    const NsJob& J = batch.j[blockIdx.y];
    int idx  = blockIdx.x * blockDim.x + threadIdx.x;
    int n    = idx >> 5;
    int lane = idx & 31;
    if (n >= N) return;
    float4 h  = *reinterpret_cast<const float4*>(J.H  + (size_t)n * kD + lane * 4);
    float4 w0 = *reinterpret_cast<const float4*>(J.Wa + lane * 4);
    float4 w1 = *reinterpret_cast<const float4*>(J.Wa + 128 + lane * 4);
    float p0 = h.x * w0.x + h.y * w0.y + h.z * w0.z + h.w * w0.w;
    float p1 = h.x * w1.x + h.y * w1.y + h.z * w1.z + h.w * w1.w;
    #pragma unroll
    for (int o = 16; o; o >>= 1) {
        p0 += __shfl_xor_sync(0xffffffffu, p0, o);
        p1 += __shfl_xor_sync(0xffffffffu, p1, o);
    }
    if (lane == 0) { J.ssrc[n] = p0; J.sdst[n] = p1 + J.ba[0]; }
}

// ============================================================
// Fused intra attention: per 4 edges (one warp):
//   w = exp(ssrc[src] + sdst[dst]);  s[dst] += w;  out[dst,:] += w * Ps[src,:]
// ============================================================
struct IfJob { const int* src; const int* dst; const float* ssrc; const float* sdst;
               const float* Ps; float* s; float* out; };
struct IfBatch { IfJob j[2]; };
__global__ void intra_fused_b(const __grid_constant__ IfBatch batch, int E)
{
    const IfJob& J = batch.j[blockIdx.y];
    int gtid = blockIdx.x * blockDim.x + threadIdx.x;
    int warp = gtid >> 5;
    int lane = gtid & 31;
    int e0 = warp * 4;

    int sI = 0, dI = 0; float w = 0.f;
    if (lane < 4) {
        int e = e0 + lane;
        sI = J.src[e];
        dI = J.dst[e];
        w = expf(J.ssrc[sI] + J.sdst[dI]);
        atomicAdd(&J.s[dI], w);
    }

    int g[4], d[4]; float wk[4]; float4 v[4];
    #pragma unroll
    for (int k = 0; k < 4; k++) {
        g[k]  = __shfl_sync(0xffffffffu, sI, k);
        d[k]  = __shfl_sync(0xffffffffu, dI, k);
        wk[k] = __shfl_sync(0xffffffffu, w,  k);
    }
    #pragma unroll
    for (int k = 0; k < 4; k++)
        v[k] = *reinterpret_cast<const float4*>(J.Ps + (size_t)g[k] * kD + lane * 4);
    #pragma unroll
    for (int k = 0; k < 4; k++) {
        float* p = J.out + (size_t)d[k] * kD + lane * 4;
        asm volatile("red.global.add.v4.f32 [%0], {%1,%2,%3,%4};"
                     :: "l"(p), "f"(wk[k] * v[k].x), "f"(wk[k] * v[k].y),
                        "f"(wk[k] * v[k].z), "f"(wk[k] * v[k].w)
                     : "memory");
    }
}

// batched finalize: out[n,:] = s[n] > 0 ? out[n,:]/s[n] + pd[n,:] : 0
struct FinJob { const float* s; const float* pd; float* out; };
struct FinBatch { FinJob j[2]; };
__global__ void finalize_b(const __grid_constant__ FinBatch batch)
{
    const FinJob& J = batch.j[blockIdx.y];
    size_t i4 = ((size_t)blockIdx.x * blockDim.x + threadIdx.x) * 4;
    int n = (int)(i4 >> 7);
    float sv = J.s[n];
    float4 o = *reinterpret_cast<float4*>(J.out + i4);
    float4 p = *reinterpret_cast<const float4*>(J.pd + i4);
    if (sv > 0.f) {
        float r = 1.f / sv;
        o.x = o.x * r + p.x;
        o.y = o.y * r + p.y;
        o.z = o.z * r + p.z;
        o.w = o.w * r + p.w;
    } else {
        o = {0.f, 0.f, 0.f, 0.f};
    }
    *reinterpret_cast<float4*>(J.out + i4) = o;
}

// ============================================================
extern "C" void kernel_launch(void* const* d_in, const int* in_sizes, int n_in,
                              void* d_out, int out_size)
{
    (void)in_sizes; (void)n_in; (void)out_size;
    float* S = nullptr;
    cudaGetSymbolAddress((void**)&S, g_scratch);

    const float* Xq   = (const float*)d_in[0];
    const int*   eq   = (const int*)d_in[1];
    const float* Xt   = (const float*)d_in[2];
    const int*   et   = (const int*)d_in[3];
    const int*   csrc = (const int*)d_in[6];
    const int*   cdst = (const int*)d_in[7];

    const float* W_ac_q = (const float*)d_in[10]; const float* b_ac_q = (const float*)d_in[11];
    const float* W_ac_t = (const float*)d_in[12]; const float* b_ac_t = (const float*)d_in[13];
    const float* W_vc_q = (const float*)d_in[14]; const float* b_vc_q = (const float*)d_in[15];
    const float* W_vc_t = (const float*)d_in[16]; const float* b_vc_t = (const float*)d_in[17];
    const float* W_mq   = (const float*)d_in[18]; const float* b_mq   = (const float*)d_in[19];
    const float* W_mt   = (const float*)d_in[20]; const float* b_mt   = (const float*)d_in[21];
    const float* W_aq   = (const float*)d_in[22]; const float* b_aq   = (const float*)d_in[23];
    const float* W_vq   = (const float*)d_in[24]; const float* b_vq   = (const float*)d_in[25];
    const float* W_at   = (const float*)d_in[26]; const float* b_at   = (const float*)d_in[27];
    const float* W_vt   = (const float*)d_in[28]; const float* b_vt   = (const float*)d_in[29];

    float* outQ = (float*)d_out;
    float* outT = outQ + SZ;

    // zero-inits
    cudaMemsetAsync(S + O_SV,  0, (O_ZEND - O_SV) * sizeof(float), 0);
    cudaMemsetAsync(S + O_ACC, 0, SZ * sizeof(float), 0);
    cudaMemsetAsync(d_out,     0, 2 * SZ * sizeof(float), 0);

    // ---- stage 1: 4 ELU node transforms ----
    {
        GemmBatch b;
        b.j[0] = {Xq, nullptr, 128, 128, W_ac_q, b_ac_q, S + O_XQ_AC, 1, nullptr, 0};
        b.j[1] = {Xt, nullptr, 128, 128, W_ac_t, b_ac_t, S + O_XT_AC, 1, nullptr, 0};
        b.j[2] = {Xq, nullptr, 128, 128, W_vc_q, b_vc_q, S + O_XQ_VC, 1, nullptr, 0};
        b.j[3] = {Xt, nullptr, 128, 128, W_vc_t, b_vc_t, S + O_XT_VC, 1, nullptr, 0};
        sgemm_b<64><<<dim3(kNQ / 64, 4), 256>>>(b);
    }

    colsum_kernel<<<kNQ / 128, 128>>>(Xq, S + O_QSUM);
    bias_mt_kernel<<<1, 128>>>(S + O_QSUM, W_mt, b_mt, S + O_BIAS);

    // ---- fused cross attention (logits + exp + denom + value scatter) ----
    cross_fused<<<(kEC / 4) * 32 / 256, 256>>>(csrc, cdst,
                                               S + O_XQ_AC, S + O_XT_AC, S + O_XQ_VC,
                                               S + O_SV, S + O_CNT, S + O_ACC);

    // ---- stage 2: merged features, K=256, normalization folded into A1 load ----
    {
        GemmBatch b;
        b.j[0] = {Xq, S + O_XT_VC, 128, 256, W_mq, b_mq,       S + O_XQM, 0, S + O_CNT, 2};
        b.j[1] = {Xt, S + O_ACC,   128, 256, W_mt, S + O_BIAS, S + O_XTM, 0, S + O_SV,  1};
        b.j[2] = b.j[0]; b.j[3] = b.j[0];
        sgemm_b<32><<<dim3(kNQ / 32, 2), 256>>>(b);
    }

    // ---- stage 3: 4 intra projections ----
    {
        GemmBatch b;
        b.j[0] = {S + O_XTM, nullptr, 128, 128, W_vt,            nullptr, S + O_PS_T, 0, nullptr, 0};
        b.j[1] = {S + O_XTM, nullptr, 128, 128, W_vt + 128 * kD, b_vt,    S + O_PD_T, 0, nullptr, 0};
        b.j[2] = {S + O_XQM, nullptr, 128, 128, W_vq,            nullptr, S + O_PS_Q, 0, nullptr, 0};
        b.j[3] = {S + O_XQM, nullptr, 128, 128, W_vq + 128 * kD, b_vq,    S + O_PD_Q, 0, nullptr, 0};
        sgemm_b<64><<<dim3(kNQ / 64, 4), 256>>>(b);
    }

    {
        NsBatch b;
        b.j[0] = {S + O_XTM, W_at, b_at, S + O_SSRC_T, S + O_SDST_T};
        b.j[1] = {S + O_XQM, W_aq, b_aq, S + O_SSRC_Q, S + O_SDST_Q};
        node_scalars_b<<<dim3((kNT * 32) / 256, 2), 256>>>(b, kNT);
    }

    // ---- fused intra attention (both graphs in one launch) ----
    {
        IfBatch b;
        b.j[0] = {et, et + kET, S + O_SSRC_T, S + O_SDST_T, S + O_PS_T, S + O_ST, outT};
        b.j[1] = {eq, eq + kEQ, S + O_SSRC_Q, S + O_SDST_Q, S + O_PS_Q, S + O_SQ, outQ};
        intra_fused_b<<<dim3((kET / 4) * 32 / 256, 2), 256>>>(b, kET);
    }

    // ---- finalize: normalize + add dst projection ----
    {
        FinBatch b;
        b.j[0] = {S + O_ST, S + O_PD_T, outT};
        b.j[1] = {S + O_SQ, S + O_PD_Q, outQ};
        finalize_b<<<dim3(SZ / 4 / 256, 2), 256>>>(b);
    }
}

// round 6
// speedup vs baseline: 1.5689x; 1.0517x over previous
#include <cuda_runtime.h>
#include <cuda_fp16.h>
#include <math.h>

// Problem constants
constexpr int kNQ = 8192;
constexpr int kNT = 8192;
constexpr int kD  = 128;
constexpr int kEC = 262144;
constexpr int kEQ = 262144;
constexpr int kET = 262144;

constexpr size_t SZ = (size_t)kNQ * kD;

// ---- scratch layout (floats) ----
// Half arrays live in the first slots (SZ halves = SZ/2 floats each, slot-aligned).
constexpr size_t O_HQ_AC = 0;              // half Xq_ac
constexpr size_t O_HT_AC = 1*SZ;           // half Xt_ac
constexpr size_t O_HQ_VC = 2*SZ;           // half Xq_vc
constexpr size_t O_XT_VC = 3*SZ;           // fp32 Xt_vc (A1 of merged-q GEMM)
constexpr size_t O_ACC   = 4*SZ;           // unnormalized Xq2t accumulator (fp32)
constexpr size_t O_XQM   = 5*SZ;
constexpr size_t O_XTM   = 6*SZ;
constexpr size_t O_HPS_T = 7*SZ;           // half Ps_T
constexpr size_t O_PD_T  = 8*SZ;
constexpr size_t O_HPS_Q = 9*SZ;           // half Ps_Q
constexpr size_t O_PD_Q  = 10*SZ;
// zero-init scalar block
constexpr size_t O_SV    = 11*SZ;
constexpr size_t O_CNT   = O_SV + kNT;
constexpr size_t O_ST    = O_CNT + kNQ;
constexpr size_t O_SQ    = O_ST + kNT;
constexpr size_t O_QSUM  = O_SQ + kNQ;
constexpr size_t O_ZEND  = O_QSUM + kD;
// non-zeroed scalars
constexpr size_t O_SSRC_T= O_ZEND;
constexpr size_t O_SDST_T= O_SSRC_T + kNT;
constexpr size_t O_SSRC_Q= O_SDST_T + kNT;
constexpr size_t O_SDST_Q= O_SSRC_Q + kNQ;
constexpr size_t O_BIAS  = O_SDST_Q + kNQ;
constexpr size_t O_TOTAL = O_BIAS + kD;

__device__ __align__(16) float g_scratch[O_TOTAL];

__device__ __forceinline__ float2 h2f(unsigned u) {
    __half2 h = *reinterpret_cast<__half2*>(&u);
    return __half22float2(h);
}

// ============================================================
// Batched tiled SGEMM, templated on BM.
// C[M,128] = act( [A0|A1][M,K] @ W[K,128] + bias )
// smode on A1 rows: 1 -> *(1/s1[r]) (0 if s<=0), 2 -> mask(s1[r]>0).
// outHalf: write C as __half instead of float.
// ============================================================
struct GemmJob {
    const float* A0; const float* A1;
    int K0; int K;
    const float* W; const float* bias;
    void* C; int act;
    const float* s1; int smode;
    int outHalf;
};
struct GemmBatch { GemmJob j[4]; };

template<int BM>
__global__ void sgemm_b(const __grid_constant__ GemmBatch batch)
{
    constexpr int TM = BM / 8;
    const GemmJob& J = batch.j[blockIdx.y];

    __shared__ float As[32][BM + 1];
    __shared__ float Bs[32][128];
    const int tid = threadIdx.x;
    const int tx = tid & 31;
    const int ty = tid >> 5;
    const int m0 = blockIdx.x * BM;

    float acc[TM][4];
    #pragma unroll
    for (int i = 0; i < TM; i++)
        #pragma unroll
        for (int j = 0; j < 4; j++) acc[i][j] = 0.f;

    const int K = J.K, K0 = J.K0;
    for (int kt = 0; kt < K; kt += 32) {
        const bool inA1 = (kt >= K0);
        const float* Ap = inA1 ? J.A1 : J.A0;
        const int ldA   = inA1 ? (K - K0) : K0;
        const int kb    = inA1 ? (kt - K0) : kt;

        #pragma unroll
        for (int i = 0; i < BM / 32; i++) {
            int t   = tid + i * 256;
            int row = t >> 3;
            int c4  = t & 7;
            float4 v = *reinterpret_cast<const float4*>(Ap + (size_t)(m0 + row) * ldA + kb + c4 * 4);
            if (inA1 && J.smode) {
                float sv = J.s1[m0 + row];
                float f = (J.smode == 1) ? (sv > 0.f ? 1.f / sv : 0.f)
                                         : (sv > 0.f ? 1.f : 0.f);
                v.x *= f; v.y *= f; v.z *= f; v.w *= f;
            }
            As[c4*4+0][row] = v.x;
            As[c4*4+1][row] = v.y;
            As[c4*4+2][row] = v.z;
            As[c4*4+3][row] = v.w;
        }
        #pragma unroll
        for (int i = 0; i < 4; i++) {
            int t  = tid + i * 256;
            int r  = t >> 5;
            int c4 = t & 31;
            float4 v = *reinterpret_cast<const float4*>(J.W + (size_t)(kt + r) * 128 + c4 * 4);
            *reinterpret_cast<float4*>(&Bs[r][c4 * 4]) = v;
        }
        __syncthreads();

        #pragma unroll
        for (int k = 0; k < 32; k++) {
            float a[TM], b[4];
            #pragma unroll
            for (int i = 0; i < TM; i++) a[i] = As[k][ty * TM + i];
            #pragma unroll
            for (int j = 0; j < 4; j++) b[j] = Bs[k][tx * 4 + j];
            #pragma unroll
            for (int i = 0; i < TM; i++)
                #pragma unroll
                for (int j = 0; j < 4; j++)
                    acc[i][j] = fmaf(a[i], b[j], acc[i][j]);
        }
        __syncthreads();
    }

    float bj[4] = {0.f, 0.f, 0.f, 0.f};
    if (J.bias) {
        #pragma unroll
        for (int j = 0; j < 4; j++) bj[j] = J.bias[tx * 4 + j];
    }
    const int act = J.act;
    #pragma unroll
    for (int i = 0; i < TM; i++) {
        int row = m0 + ty * TM + i;
        float v0 = acc[i][0] + bj[0];
        float v1 = acc[i][1] + bj[1];
        float v2 = acc[i][2] + bj[2];
        float v3 = acc[i][3] + bj[3];
        if (act) {
            v0 = v0 > 0.f ? v0 : expm1f(v0);
            v1 = v1 > 0.f ? v1 : expm1f(v1);
            v2 = v2 > 0.f ? v2 : expm1f(v2);
            v3 = v3 > 0.f ? v3 : expm1f(v3);
        }
        if (J.outHalf) {
            __half2 h0 = __floats2half2_rn(v0, v1);
            __half2 h1 = __floats2half2_rn(v2, v3);
            uint2 o;
            o.x = *reinterpret_cast<unsigned*>(&h0);
            o.y = *reinterpret_cast<unsigned*>(&h1);
            *reinterpret_cast<uint2*>((__half*)J.C + (size_t)row * 128 + tx * 4) = o;
        } else {
            float4 o = {v0, v1, v2, v3};
            *reinterpret_cast<float4*>((float*)J.C + (size_t)row * 128 + tx * 4) = o;
        }
    }
}

__global__ void colsum_kernel(const float* __restrict__ X, float* __restrict__ sums)
{
    int j  = threadIdx.x;
    int r0 = blockIdx.x * 128;
    float s = 0.f;
    for (int r = 0; r < 128; r++) s += X[(size_t)(r0 + r) * kD + j];
    atomicAdd(&sums[j], s);
}

__global__ void bias_mt_kernel(const float* __restrict__ qsum, const float* __restrict__ W_mt,
                               const float* __restrict__ b_mt, float* __restrict__ be)
{
    int j = threadIdx.x;
    float s = b_mt[j];
    const float inv = 1.0f / (float)kNQ;
    for (int k = 0; k < kD; k++)
        s = fmaf(qsum[k] * inv, W_mt[(size_t)(256 + k) * kD + j], s);
    be[j] = s;
}

// ============================================================
// Fused cross attention, fp16 gathers, fp32 accumulate/scatter.
// per 4 edges (one warp):
//   p = dot(Aq[src], At[dst]);  w = exp(p)   (no max shift — range-safe)
//   s_v[dst] += w;  cnt[src] += 1;  acc[dst,:] += w * Vq[src,:]
// ============================================================
__global__ void cross_fused(const int* __restrict__ src, const int* __restrict__ dst,
                            const __half* __restrict__ Aq, const __half* __restrict__ At,
                            const __half* __restrict__ Vq,
                            float* __restrict__ s_v, float* __restrict__ cnt_u,
                            float* __restrict__ acc)
{
    int gtid = blockIdx.x * blockDim.x + threadIdx.x;
    int warp = gtid >> 5;
    int lane = gtid & 31;
    int e0 = warp * 4;

    int idxv = 0;
    if (lane < 8) {
        int e = e0 + (lane & 3);
        idxv = (lane < 4) ? src[e] : dst[e];
    }
    int uu[4], dd[4];
    #pragma unroll
    for (int k = 0; k < 4; k++) {
        uu[k] = __shfl_sync(0xffffffffu, idxv, k);
        dd[k] = __shfl_sync(0xffffffffu, idxv, 4 + k);
    }

    // 12 independent 8B row-slice gathers batched up front (lane covers 4 halves)
    uint2 a[4], b[4], v[4];
    #pragma unroll
    for (int k = 0; k < 4; k++) {
        a[k] = *reinterpret_cast<const uint2*>(Aq + (size_t)uu[k] * kD + lane * 4);
        b[k] = *reinterpret_cast<const uint2*>(At + (size_t)dd[k] * kD + lane * 4);
        v[k] = *reinterpret_cast<const uint2*>(Vq + (size_t)uu[k] * kD + lane * 4);
    }

    float w[4];
    #pragma unroll
    for (int k = 0; k < 4; k++) {
        float2 a0 = h2f(a[k].x), a1 = h2f(a[k].y);
        float2 b0 = h2f(b[k].x), b1 = h2f(b[k].y);
        w[k] = a0.x * b0.x + a0.y * b0.y + a1.x * b1.x + a1.y * b1.y;
    }
    #pragma unroll
    for (int o = 16; o; o >>= 1) {
        #pragma unroll
        for (int k = 0; k < 4; k++) w[k] += __shfl_xor_sync(0xffffffffu, w[k], o);
    }
    #pragma unroll
    for (int k = 0; k < 4; k++) w[k] = expf(w[k]);

    // lanes 0-3 update scalar accumulators for their own edge
    {
        float wl = w[0]; int dl = dd[0], ul = uu[0];
        if (lane == 1) { wl = w[1]; dl = dd[1]; ul = uu[1]; }
        if (lane == 2) { wl = w[2]; dl = dd[2]; ul = uu[2]; }
        if (lane == 3) { wl = w[3]; dl = dd[3]; ul = uu[3]; }
        if (lane < 4) {
            atomicAdd(&s_v[dl], wl);
            atomicAdd(&cnt_u[ul], 1.0f);
        }
    }

    #pragma unroll
    for (int k = 0; k < 4; k++) {
        float2 v0 = h2f(v[k].x), v1 = h2f(v[k].y);
        float* p = acc + (size_t)dd[k] * kD + lane * 4;
        asm volatile("red.global.add.v4.f32 [%0], {%1,%2,%3,%4};"
                     :: "l"(p), "f"(w[k] * v0.x), "f"(w[k] * v0.y),
                        "f"(w[k] * v1.x), "f"(w[k] * v1.y)
                     : "memory");
    }
}

// batched per-node attention scalars (fp32 inputs)
struct NsJob { const float* H; const float* Wa; const float* ba; float* ssrc; float* sdst; };
struct NsBatch { NsJob j[2]; };
__global__ void node_scalars_b(const __grid_constant__ NsBatch batch, int N)
{
    const NsJob& J = batch.j[blockIdx.y];
    int idx  = blockIdx.x * blockDim.x + threadIdx.x;
    int n    = idx >> 5;
    int lane = idx & 31;
    if (n >= N) return;
    float4 h  = *reinterpret_cast<const float4*>(J.H  + (size_t)n * kD + lane * 4);
    float4 w0 = *reinterpret_cast<const float4*>(J.Wa + lane * 4);
    float4 w1 = *reinterpret_cast<const float4*>(J.Wa + 128 + lane * 4);
    float p0 = h.x * w0.x + h.y * w0.y + h.z * w0.z + h.w * w0.w;
    float p1 = h.x * w1.x + h.y * w1.y + h.z * w1.z + h.w * w1.w;
    #pragma unroll
    for (int o = 16; o; o >>= 1) {
        p0 += __shfl_xor_sync(0xffffffffu, p0, o);
        p1 += __shfl_xor_sync(0xffffffffu, p1, o);
    }
    if (lane == 0) { J.ssrc[n] = p0; J.sdst[n] = p1 + J.ba[0]; }
}

// ============================================================
// Fused intra attention, fp16 value gathers:
//   w = exp(ssrc[src] + sdst[dst]);  s[dst] += w;  out[dst,:] += w * Ps[src,:]
// ============================================================
struct IfJob { const int* src; const int* dst; const float* ssrc; const float* sdst;
               const __half* Ps; float* s; float* out; };
struct IfBatch { IfJob j[2]; };
__global__ void intra_fused_b(const __grid_constant__ IfBatch batch, int E)
{
    const IfJob& J = batch.j[blockIdx.y];
    int gtid = blockIdx.x * blockDim.x + threadIdx.x;
    int warp = gtid >> 5;
    int lane = gtid & 31;
    int e0 = warp * 4;

    int sI = 0, dI = 0; float w = 0.f;
    if (lane < 4) {
        int e = e0 + lane;
        sI = J.src[e];
        dI = J.dst[e];
        w = expf(J.ssrc[sI] + J.sdst[dI]);
        atomicAdd(&J.s[dI], w);
    }

    int g[4], d[4]; float wk[4]; uint2 v[4];
    #pragma unroll
    for (int k = 0; k < 4; k++) {
        g[k]  = __shfl_sync(0xffffffffu, sI, k);
        d[k]  = __shfl_sync(0xffffffffu, dI, k);
        wk[k] = __shfl_sync(0xffffffffu, w,  k);
    }
    #pragma unroll
    for (int k = 0; k < 4; k++)
        v[k] = *reinterpret_cast<const uint2*>(J.Ps + (size_t)g[k] * kD + lane * 4);
    #pragma unroll
    for (int k = 0; k < 4; k++) {
        float2 v0 = h2f(v[k].x), v1 = h2f(v[k].y);
        float* p = J.out + (size_t)d[k] * kD + lane * 4;
        asm volatile("red.global.add.v4.f32 [%0], {%1,%2,%3,%4};"
                     :: "l"(p), "f"(wk[k] * v0.x), "f"(wk[k] * v0.y),
                        "f"(wk[k] * v1.x), "f"(wk[k] * v1.y)
                     : "memory");
    }
}

// batched finalize: out[n,:] = s[n] > 0 ? out[n,:]/s[n] + pd[n,:] : 0
struct FinJob { const float* s; const float* pd; float* out; };
struct FinBatch { FinJob j[2]; };
__global__ void finalize_b(const __grid_constant__ FinBatch batch)
{
    const FinJob& J = batch.j[blockIdx.y];
    size_t i4 = ((size_t)blockIdx.x * blockDim.x + threadIdx.x) * 4;
    int n = (int)(i4 >> 7);
    float sv = J.s[n];
    float4 o = *reinterpret_cast<float4*>(J.out + i4);
    float4 p = *reinterpret_cast<const float4*>(J.pd + i4);
    if (sv > 0.f) {
        float r = 1.f / sv;
        o.x = o.x * r + p.x;
        o.y = o.y * r + p.y;
        o.z = o.z * r + p.z;
        o.w = o.w * r + p.w;
    } else {
        o = {0.f, 0.f, 0.f, 0.f};
    }
    *reinterpret_cast<float4*>(J.out + i4) = o;
}

// ============================================================
extern "C" void kernel_launch(void* const* d_in, const int* in_sizes, int n_in,
                              void* d_out, int out_size)
{
    (void)in_sizes; (void)n_in; (void)out_size;
    float* S = nullptr;
    cudaGetSymbolAddress((void**)&S, g_scratch);

    const float* Xq   = (const float*)d_in[0];
    const int*   eq   = (const int*)d_in[1];
    const float* Xt   = (const float*)d_in[2];
    const int*   et   = (const int*)d_in[3];
    const int*   csrc = (const int*)d_in[6];
    const int*   cdst = (const int*)d_in[7];

    const float* W_ac_q = (const float*)d_in[10]; const float* b_ac_q = (const float*)d_in[11];
    const float* W_ac_t = (const float*)d_in[12]; const float* b_ac_t = (const float*)d_in[13];
    const float* W_vc_q = (const float*)d_in[14]; const float* b_vc_q = (const float*)d_in[15];
    const float* W_vc_t = (const float*)d_in[16]; const float* b_vc_t = (const float*)d_in[17];
    const float* W_mq   = (const float*)d_in[18]; const float* b_mq   = (const float*)d_in[19];
    const float* W_mt   = (const float*)d_in[20]; const float* b_mt   = (const float*)d_in[21];
    const float* W_aq   = (const float*)d_in[22]; const float* b_aq   = (const float*)d_in[23];
    const float* W_vq   = (const float*)d_in[24]; const float* b_vq   = (const float*)d_in[25];
    const float* W_at   = (const float*)d_in[26]; const float* b_at   = (const float*)d_in[27];
    const float* W_vt   = (const float*)d_in[28]; const float* b_vt   = (const float*)d_in[29];

    float* outQ = (float*)d_out;
    float* outT = outQ + SZ;

    __half* HQ_AC = (__half*)(S + O_HQ_AC);
    __half* HT_AC = (__half*)(S + O_HT_AC);
    __half* HQ_VC = (__half*)(S + O_HQ_VC);
    __half* HPS_T = (__half*)(S + O_HPS_T);
    __half* HPS_Q = (__half*)(S + O_HPS_Q);

    // zero-inits
    cudaMemsetAsync(S + O_SV,  0, (O_ZEND - O_SV) * sizeof(float), 0);
    cudaMemsetAsync(S + O_ACC, 0, SZ * sizeof(float), 0);
    cudaMemsetAsync(d_out,     0, 2 * SZ * sizeof(float), 0);

    // ---- stage 1: 4 ELU node transforms (3 half outputs, 1 fp32) ----
    {
        GemmBatch b;
        b.j[0] = {Xq, nullptr, 128, 128, W_ac_q, b_ac_q, HQ_AC,      1, nullptr, 0, 1};
        b.j[1] = {Xt, nullptr, 128, 128, W_ac_t, b_ac_t, HT_AC,      1, nullptr, 0, 1};
        b.j[2] = {Xq, nullptr, 128, 128, W_vc_q, b_vc_q, HQ_VC,      1, nullptr, 0, 1};
        b.j[3] = {Xt, nullptr, 128, 128, W_vc_t, b_vc_t, S + O_XT_VC, 1, nullptr, 0, 0};
        sgemm_b<64><<<dim3(kNQ / 64, 4), 256>>>(b);
    }

    colsum_kernel<<<kNQ / 128, 128>>>(Xq, S + O_QSUM);
    bias_mt_kernel<<<1, 128>>>(S + O_QSUM, W_mt, b_mt, S + O_BIAS);

    // ---- fused cross attention ----
    cross_fused<<<(kEC / 4) * 32 / 256, 256>>>(csrc, cdst, HQ_AC, HT_AC, HQ_VC,
                                               S + O_SV, S + O_CNT, S + O_ACC);

    // ---- stage 2: merged features, K=256, normalization folded into A1 load ----
    {
        GemmBatch b;
        b.j[0] = {Xq, S + O_XT_VC, 128, 256, W_mq, b_mq,       S + O_XQM, 0, S + O_CNT, 2, 0};
        b.j[1] = {Xt, S + O_ACC,   128, 256, W_mt, S + O_BIAS, S + O_XTM, 0, S + O_SV,  1, 0};
        b.j[2] = b.j[0]; b.j[3] = b.j[0];
        sgemm_b<32><<<dim3(kNQ / 32, 2), 256>>>(b);
    }

    // ---- stage 3: 4 intra projections (Ps as half, Pd fp32) ----
    {
        GemmBatch b;
        b.j[0] = {S + O_XTM, nullptr, 128, 128, W_vt,            nullptr, HPS_T,      0, nullptr, 0, 1};
        b.j[1] = {S + O_XTM, nullptr, 128, 128, W_vt + 128 * kD, b_vt,    S + O_PD_T, 0, nullptr, 0, 0};
        b.j[2] = {S + O_XQM, nullptr, 128, 128, W_vq,            nullptr, HPS_Q,      0, nullptr, 0, 1};
        b.j[3] = {S + O_XQM, nullptr, 128, 128, W_vq + 128 * kD, b_vq,    S + O_PD_Q, 0, nullptr, 0, 0};
        sgemm_b<64><<<dim3(kNQ / 64, 4), 256>>>(b);
    }

    {
        NsBatch b;
        b.j[0] = {S + O_XTM, W_at, b_at, S + O_SSRC_T, S + O_SDST_T};
        b.j[1] = {S + O_XQM, W_aq, b_aq, S + O_SSRC_Q, S + O_SDST_Q};
        node_scalars_b<<<dim3((kNT * 32) / 256, 2), 256>>>(b, kNT);
    }

    // ---- fused intra attention (both graphs in one launch) ----
    {
        IfBatch b;
        b.j[0] = {et, et + kET, S + O_SSRC_T, S + O_SDST_T, HPS_T, S + O_ST, outT};
        b.j[1] = {eq, eq + kEQ, S + O_SSRC_Q, S + O_SDST_Q, HPS_Q, S + O_SQ, outQ};
        intra_fused_b<<<dim3((kET / 4) * 32 / 256, 2), 256>>>(b, kET);
    }

    // ---- finalize: normalize + add dst projection ----
    {
        FinBatch b;
        b.j[0] = {S + O_ST, S + O_PD_T, outT};
        b.j[1] = {S + O_SQ, S + O_PD_Q, outQ};
        finalize_b<<<dim3(SZ / 4 / 256, 2), 256>>>(b);
    }
}